// round 11
// baseline (speedup 1.0000x reference)
#include <cuda_runtime.h>
#include <cuda_fp16.h>
#include <cstdint>
#include <cstddef>

#define HEADS 16
#define TSEQ  2048
#define CEMB  1024
#define DH    64
#define BATCH 4
#define BH    (BATCH*HEADS)   // 64
#define BT    (BATCH*TSEQ)    // 8192
#define NT2   16              // 128-row t-tiles
#define NW4   (HEADS*CEMB*DH/4)

// ---------------- scratch (device globals; allocation-free) ----------------
__device__ __align__(16) __half g_xh [(size_t)BT*CEMB];
__device__ __align__(16) __half g_wh [(size_t)3*HEADS*CEMB*DH];
__device__ __align__(16) __half g_wph[(size_t)CEMB*CEMB];
__device__ __align__(16) __half g_qh [(size_t)BH*TSEQ*DH];
__device__ __align__(16) __half g_kh [(size_t)BH*TSEQ*DH];
__device__ __align__(16) float  g_v  [(size_t)BH*TSEQ*DH];
__device__ __align__(16) __half g_vh [(size_t)BH*TSEQ*DH];
__device__ __align__(16) __half g_yh [(size_t)BT*CEMB];
__device__ float g_Zpart[(size_t)BH*NT2*TSEQ];
__device__ float g_Z[(size_t)BH*TSEQ];

// ---------------- helpers ----------------
__device__ __forceinline__ uint32_t smem_u32(const void* p) {
    return (uint32_t)__cvta_generic_to_shared(p);
}
__device__ __forceinline__ void cpa16(uint32_t dst, const void* src) {
    asm volatile("cp.async.cg.shared.global [%0], [%1], 16;" :: "r"(dst), "l"(src));
}
#define CP_COMMIT() asm volatile("cp.async.commit_group;" ::: "memory")
#define CP_WAIT1()  asm volatile("cp.async.wait_group 1;" ::: "memory")
#define CP_WAIT0()  asm volatile("cp.async.wait_group 0;" ::: "memory")

__device__ __forceinline__ float fast_exp(float x) {
    x = fmaxf(-60.f, fminf(60.f, x));
    float z = x * 1.4426950408889634f;
    float n = rintf(z);
    float t = (z - n) * 0.6931471805599453f;
    float p = 1.3888889e-3f;
    p = fmaf(p, t, 8.3333333e-3f);
    p = fmaf(p, t, 4.1666667e-2f);
    p = fmaf(p, t, 1.6666667e-1f);
    p = fmaf(p, t, 0.5f);
    p = fmaf(p, t, 1.0f);
    p = fmaf(p, t, 1.0f);
    return p * __int_as_float(((int)n + 127) << 23);
}
__device__ __forceinline__ void ldsm4(uint32_t r[4], uint32_t a) {
    asm volatile("ldmatrix.sync.aligned.m8n8.x4.shared.b16 {%0,%1,%2,%3},[%4];"
                 : "=r"(r[0]), "=r"(r[1]), "=r"(r[2]), "=r"(r[3]) : "r"(a));
}
__device__ __forceinline__ void ldsm4t(uint32_t r[4], uint32_t a) {
    asm volatile("ldmatrix.sync.aligned.m8n8.x4.trans.shared.b16 {%0,%1,%2,%3},[%4];"
                 : "=r"(r[0]), "=r"(r[1]), "=r"(r[2]), "=r"(r[3]) : "r"(a));
}
__device__ __forceinline__ void mma16816(float c[4], const uint32_t a[4],
                                         uint32_t b0, uint32_t b1) {
    asm volatile(
        "mma.sync.aligned.m16n8k16.row.col.f32.f16.f16.f32 "
        "{%0,%1,%2,%3},{%4,%5,%6,%7},{%8,%9},{%0,%1,%2,%3};"
        : "+f"(c[0]), "+f"(c[1]), "+f"(c[2]), "+f"(c[3])
        : "r"(a[0]), "r"(a[1]), "r"(a[2]), "r"(a[3]), "r"(b0), "r"(b1));
}

// ==================== prep kernels ====================
__global__ void cvt_kernel(const float* __restrict__ src, int n4, int sel)
{
    int i = blockIdx.x * blockDim.x + threadIdx.x;
    if (i >= n4) return;
    __half* d = (sel == 0) ? g_xh : g_wph;
    float4 v = ((const float4*)src)[i];
    __half2 a; a.x = __float2half(v.x); a.y = __float2half(v.y);
    __half2 b; b.x = __float2half(v.z); b.y = __float2half(v.w);
    ((__half2*)d)[(size_t)i * 2]     = a;
    ((__half2*)d)[(size_t)i * 2 + 1] = b;
}
__global__ void cvtw_kernel(const float* __restrict__ Wq, const float* __restrict__ Wk,
                            const float* __restrict__ Wv)
{
    int i = blockIdx.x * blockDim.x + threadIdx.x;
    if (i >= 3 * NW4) return;
    int which = i / NW4, j = i - which * NW4;
    const float* src = (which == 0) ? Wq : (which == 1) ? Wk : Wv;
    float4 v = ((const float4*)src)[j];
    __half2 a; a.x = __float2half(v.x); a.y = __float2half(v.y);
    __half2 b; b.x = __float2half(v.z); b.y = __float2half(v.w);
    ((__half2*)g_wh)[(size_t)i * 2]     = a;
    ((__half2*)g_wh)[(size_t)i * 2 + 1] = b;
}

// ==================== K1: QKV projection, 128x128 tile (R10 version) ========
__global__ __launch_bounds__(256) void qkv_kernel()
{
    __shared__ alignas(16) __half A[3][128*24];
    __shared__ alignas(16) __half B[3][16*136];
    const int tid = threadIdx.x, w = tid >> 5, lane = tid & 31;
    const int wm = w & 3, wn = w >> 2;
    const int m0 = blockIdx.x * 128;
    const int z = blockIdx.y, which = z >> 3, np = z & 7;
    const int h0 = np * 2;
    const __half* W0 = g_wh + (size_t)(which * HEADS + h0) * CEMB * DH;

    float acc[2][8][4] = {};
    uint32_t aB[2], bB[4];
#pragma unroll
    for (int mt = 0; mt < 2; ++mt) {
        int ar = wm*32 + mt*16 + (lane & 15), ak = (lane >> 4) * 8;
        aB[mt] = smem_u32(&A[0][ar*24 + ak]);
    }
#pragma unroll
    for (int blk = 0; blk < 4; ++blk) {
        int br = (lane & 15), bc = wn*64 + blk*16 + ((lane & 16) ? 8 : 0);
        bB[blk] = smem_u32(&B[0][br*136 + bc]);
    }
    const int arL = tid >> 1, asL = (tid & 1) * 8;
    const int brL = tid >> 4, bsL = (tid & 15) * 8;
    const int bhead = bsL >> 6, bd = bsL & 63;
    const __half* Wsrc = W0 + (size_t)bhead * CEMB * DH;

    auto load_chunk = [&](int c, int stg) {
        const int k0 = c * 16;
        cpa16(smem_u32(&A[stg][arL*24 + asL]), &g_xh[(size_t)(m0 + arL)*CEMB + k0 + asL]);
        cpa16(smem_u32(&B[stg][brL*136 + bsL]), &Wsrc[(size_t)(k0 + brL)*DH + bd]);
    };

    load_chunk(0, 0); CP_COMMIT();
    load_chunk(1, 1); CP_COMMIT();
    for (int c = 0; c < 64; ++c) {
        CP_WAIT1();
        __syncthreads();
        if (c + 2 < 64) load_chunk(c + 2, (c + 2) % 3);
        CP_COMMIT();
        const uint32_t aS = (c % 3) * (uint32_t)(128*24*2);
        const uint32_t bS = (c % 3) * (uint32_t)(16*136*2);
        uint32_t ah[2][4], bh[4][4];
#pragma unroll
        for (int mt = 0; mt < 2; ++mt) ldsm4(ah[mt], aB[mt] + aS);
#pragma unroll
        for (int blk = 0; blk < 4; ++blk) ldsm4t(bh[blk], bB[blk] + bS);
#pragma unroll
        for (int mt = 0; mt < 2; ++mt)
#pragma unroll
            for (int nt = 0; nt < 8; ++nt) {
                int blk = nt >> 1, p2 = (nt & 1) * 2;
                mma16816(acc[mt][nt], ah[mt], bh[blk][p2], bh[blk][p2+1]);
            }
    }
#pragma unroll
    for (int mt = 0; mt < 2; ++mt)
#pragma unroll
        for (int nt = 0; nt < 8; ++nt)
#pragma unroll
            for (int half = 0; half < 2; ++half) {
                int m = m0 + wm*32 + mt*16 + (lane >> 2) + half*8;
                int n = wn*64 + nt*8 + (lane & 3)*2;
                int h = h0 + (n >> 6), d = n & 63;
                int b = m >> 11, t = m & (TSEQ - 1);
                size_t base = (((size_t)(b*HEADS + h))*TSEQ + t)*DH + d;
                float c0 = acc[mt][nt][half*2], c1 = acc[mt][nt][half*2+1];
                if (which == 2) {
                    *(float2*)&g_v[base] = make_float2(c0, c1);
                } else {
                    __half2 p2; p2.x = __float2half(c0); p2.y = __float2half(c1);
                    __half* dst = (which == 0) ? g_qh : g_kh;
                    *(__half2*)&dst[base] = p2;
                }
            }
}

// ==================== K2: scores_z — Z column partials only (no P store) ====
// grid(272, 64). tile 128 t-rows x 64 s-cols, causal tiles only.
__global__ __launch_bounds__(256) void scores_kernel()
{
    __shared__ alignas(16) __half A[128*72];
    __shared__ alignas(16) __half B[64*72];
    __shared__ float red[8][32];
    const int tid = threadIdx.x, w = tid >> 5, lane = tid & 31;
    const int wm = w & 3, wn = w >> 2;
    const int bh_ = blockIdx.y;
    int p = blockIdx.x;
    int tt = (int)sqrtf((float)p);
    while (tt*tt + tt > p) --tt;
    while ((tt+1)*(tt+1) + (tt+1) <= p) ++tt;
    const int ss = p - tt*tt - tt;
    const int t0 = tt * 128, s0 = ss * 64;
    const __half* qh = g_qh + (size_t)bh_*TSEQ*DH;
    const __half* kh = g_kh + (size_t)bh_*TSEQ*DH;

    float acc[2][4][4] = {};
    uint32_t aB[2], bB[2];
#pragma unroll
    for (int mt = 0; mt < 2; ++mt) {
        int ar = wm*32 + mt*16 + (lane & 15), ak = (lane >> 4) * 8;
        aB[mt] = smem_u32(&A[ar*72 + ak]);
    }
#pragma unroll
    for (int blk = 0; blk < 2; ++blk) {
        int br = wn*32 + blk*16 + (lane & 7) + ((lane & 16) ? 8 : 0);
        int bk = (lane & 8) ? 8 : 0;
        bB[blk] = smem_u32(&B[br*72 + bk]);
    }

#pragma unroll
    for (int i = 0; i < 4; ++i) {
        int idx = tid + i * 256, r = idx >> 3, sg = (idx & 7) * 8;
        cpa16(smem_u32(&A[r*72 + sg]), &qh[(size_t)(t0 + r)*DH + sg]);
    }
#pragma unroll
    for (int i = 0; i < 2; ++i) {
        int idx = tid + i * 256, r = idx >> 3, sg = (idx & 7) * 8;
        cpa16(smem_u32(&B[r*72 + sg]), &kh[(size_t)(s0 + r)*DH + sg]);
    }
    CP_COMMIT(); CP_WAIT0();
    __syncthreads();
#pragma unroll
    for (int k16 = 0; k16 < 4; ++k16) {
        uint32_t ah[2][4], bhf[2][4];
#pragma unroll
        for (int mt = 0; mt < 2; ++mt) ldsm4(ah[mt], aB[mt] + k16*32);
#pragma unroll
        for (int blk = 0; blk < 2; ++blk) ldsm4(bhf[blk], bB[blk] + k16*32);
#pragma unroll
        for (int mt = 0; mt < 2; ++mt)
#pragma unroll
            for (int nt = 0; nt < 4; ++nt) {
                int blk = nt >> 1, p2 = (nt & 1) * 2;
                mma16816(acc[mt][nt], ah[mt], bhf[blk][p2], bhf[blk][p2+1]);
            }
    }

    const float scale = 0.03125f;
    float cs[4][2] = {};
#pragma unroll
    for (int mt = 0; mt < 2; ++mt)
#pragma unroll
        for (int nt = 0; nt < 4; ++nt)
#pragma unroll
            for (int half = 0; half < 2; ++half) {
                int t = t0 + wm*32 + mt*16 + (lane >> 2) + half*8;
                int s = s0 + wn*32 + nt*8 + (lane & 3)*2;
                float e0 = (s     <= t) ? fast_exp(acc[mt][nt][half*2]   * scale) : 0.f;
                float e1 = (s + 1 <= t) ? fast_exp(acc[mt][nt][half*2+1] * scale) : 0.f;
                cs[nt][0] += e0; cs[nt][1] += e1;
            }
#pragma unroll
    for (int nt = 0; nt < 4; ++nt)
#pragma unroll
        for (int par = 0; par < 2; ++par) {
            float v = cs[nt][par];
            v += __shfl_xor_sync(0xffffffffu, v, 4);
            v += __shfl_xor_sync(0xffffffffu, v, 8);
            v += __shfl_xor_sync(0xffffffffu, v, 16);
            if (lane < 4) red[w][nt*8 + (lane & 3)*2 + par] = v;
        }
    __syncthreads();
    if (tid < 64) {
        int col = tid, wh = col >> 5;
        float s = red[wh*4+0][col & 31] + red[wh*4+1][col & 31]
                + red[wh*4+2][col & 31] + red[wh*4+3][col & 31];
        g_Zpart[((size_t)bh_*NT2 + tt)*TSEQ + s0 + col] = s;
    }
}

// ==================== K3a: Z reduce (deterministic) ====================
__global__ void zreduce_kernel()
{
    int idx = blockIdx.x * blockDim.x + threadIdx.x;
    if (idx >= BH * TSEQ) return;
    int bh_ = idx >> 11, s = idx & (TSEQ - 1), ttmin = s >> 7;
    float sum = 0.f;
    for (int tt = ttmin; tt < NT2; ++tt)
        sum += g_Zpart[((size_t)bh_*NT2 + tt)*TSEQ + s];
    g_Z[idx] = sum;
}

// ==================== K3b: v/Z -> single fp16 plane ====================
__global__ void vscale_kernel()
{
    int i4 = blockIdx.x * blockDim.x + threadIdx.x;
    if (i4 >= BH * TSEQ * DH / 4) return;
    float rz = 1.0f / g_Z[i4 >> 4];
    float4 v = ((const float4*)g_v)[i4];
    __half2 a; a.x = __float2half(v.x * rz); a.y = __float2half(v.y * rz);
    __half2 b; b.x = __float2half(v.z * rz); b.y = __float2half(v.w * rz);
    ((__half2*)g_vh)[i4 * 2]     = a;
    ((__half2*)g_vh)[i4 * 2 + 1] = b;
}

// ==================== K4: fused pv — recompute S, exp, Ps in smem, PV =======
// grid(16, 64). CTA: 128 t-rows x 64 d. s-chunks of 32, nsteps = 4(tt+1).
__global__ __launch_bounds__(256) void pv_kernel()
{
    __shared__ alignas(16) __half Q [128*72];      // 18432 B
    __shared__ alignas(16) __half K2[2][32*72];    //  9216
    __shared__ alignas(16) __half V2[2][32*72];    //  9216
    __shared__ alignas(16) __half Ps[128*40];      // 10240  (total 47104)
    const int tid = threadIdx.x, w = tid >> 5, lane = tid & 31;
    const int wm = w & 3, wn = w >> 2;
    const int tt = 15 - blockIdx.x;
    const int bh_ = blockIdx.y;
    const int t0 = tt * 128;
    const __half* qh = g_qh + (size_t)bh_*TSEQ*DH;
    const __half* kh = g_kh + (size_t)bh_*TSEQ*DH;
    const __half* vh = g_vh + (size_t)bh_*TSEQ*DH;

    float acc[2][4][4] = {};   // y accumulators
    // frag addrs
    uint32_t aQ[2], bK, aP[2], bV[2];
#pragma unroll
    for (int mt = 0; mt < 2; ++mt) {
        int ar = wm*32 + mt*16 + (lane & 15), ak = (lane >> 4) * 8;
        aQ[mt] = smem_u32(&Q[ar*72 + ak]);
        aP[mt] = smem_u32(&Ps[ar*40 + ak]);
    }
    {   // S-phase B (natural: row=s(n), col=d(k)); warp n-width 16
        int br = wn*16 + (lane & 7) + ((lane & 16) ? 8 : 0);
        int bk = (lane & 8) ? 8 : 0;
        bK = smem_u32(&K2[0][br*72 + bk]);
    }
#pragma unroll
    for (int blk = 0; blk < 2; ++blk) {  // PV-phase B (trans: row=s(k), col=d(n))
        int br = (lane & 15), bc = wn*32 + blk*16 + ((lane & 16) ? 8 : 0);
        bV[blk] = smem_u32(&V2[0][br*72 + bc]);
    }
    const int rL = tid >> 3, sgL = (tid & 7) * 8;   // K/V chunk loader (256 tasks each? 32r x 8seg = 256)

    // Q load: 128 rows x 8 segs = 1024 tasks
#pragma unroll
    for (int i = 0; i < 4; ++i) {
        int idx = tid + i * 256, r = idx >> 3, sg = (idx & 7) * 8;
        cpa16(smem_u32(&Q[r*72 + sg]), &qh[(size_t)(t0 + r)*DH + sg]);
    }
    // chunk 0 K/V: thread tid<256 covers K (first 256 tasks? K has 32*8=256 tasks) — split:
    // K tasks: tid maps r=tid>>3 (0..31), sg=(tid&7)*8  -> all 256 threads, 1 task each
    cpa16(smem_u32(&K2[0][rL*72 + sgL]), &kh[(size_t)rL*DH + sgL]);
    cpa16(smem_u32(&V2[0][rL*72 + sgL]), &vh[(size_t)rL*DH + sgL]);
    CP_COMMIT();

    const int nsteps = 4 * (tt + 1);
    const float scale = 0.03125f;
    for (int c = 0; c < nsteps; ++c) {
        CP_WAIT0();
        __syncthreads();   // chunk c K/V (+Q on c=0) visible; Ps(c-1) fully consumed
        if (c + 1 < nsteps) {
            const int s0n = (c + 1) * 32, stg = (c + 1) & 1;
            cpa16(smem_u32(&K2[stg][rL*72 + sgL]), &kh[(size_t)(s0n + rL)*DH + sgL]);
            cpa16(smem_u32(&V2[stg][rL*72 + sgL]), &vh[(size_t)(s0n + rL)*DH + sgL]);
            CP_COMMIT();
        }
        const uint32_t kS = (uint32_t)(c & 1) * (32*72*2);
        // ---- S-MMA: Sc[128,32] = Q[128,64] @ K[32,64]^T ----
        float accs[2][2][4] = {};
#pragma unroll
        for (int k16 = 0; k16 < 4; ++k16) {
            uint32_t qf[2][4], kf[4];
#pragma unroll
            for (int mt = 0; mt < 2; ++mt) ldsm4(qf[mt], aQ[mt] + k16*32);
            ldsm4(kf, bK + kS + k16*32);
#pragma unroll
            for (int mt = 0; mt < 2; ++mt)
#pragma unroll
                for (int nt = 0; nt < 2; ++nt)
                    mma16816(accs[mt][nt], qf[mt], kf[nt*2], kf[nt*2+1]);
        }
        // ---- exp + mask -> Ps (fp16, same rounding as old g_P store) ----
        const int s0 = c * 32;
#pragma unroll
        for (int mt = 0; mt < 2; ++mt)
#pragma unroll
            for (int nt = 0; nt < 2; ++nt)
#pragma unroll
                for (int half = 0; half < 2; ++half) {
                    int tl = wm*32 + mt*16 + (lane >> 2) + half*8;
                    int sl = wn*16 + nt*8 + (lane & 3)*2;
                    int t = t0 + tl, s = s0 + sl;
                    float e0 = (s     <= t) ? fast_exp(accs[mt][nt][half*2]   * scale) : 0.f;
                    float e1 = (s + 1 <= t) ? fast_exp(accs[mt][nt][half*2+1] * scale) : 0.f;
                    __half2 p2; p2.x = __float2half(e0); p2.y = __float2half(e1);
                    *(__half2*)&Ps[tl*40 + sl] = p2;
                }
        __syncthreads();   // Ps complete
        // ---- PV-MMA: y += Ps[128,32] @ V[32,64] ----
        const uint32_t vS = (uint32_t)(c & 1) * (32*72*2);
#pragma unroll
        for (int k16 = 0; k16 < 2; ++k16) {
            uint32_t pf[2][4], vf[2][4];
#pragma unroll
            for (int mt = 0; mt < 2; ++mt) ldsm4(pf[mt], aP[mt] + k16*32);
#pragma unroll
            for (int blk = 0; blk < 2; ++blk) ldsm4t(vf[blk], bV[blk] + vS + k16*2304);
#pragma unroll
            for (int mt = 0; mt < 2; ++mt)
#pragma unroll
                for (int nt = 0; nt < 4; ++nt) {
                    int blk = nt >> 1, p2 = (nt & 1) * 2;
                    mma16816(acc[mt][nt], pf[mt], vf[blk][p2], vf[blk][p2+1]);
                }
        }
    }
    const int b = bh_ >> 4, h = bh_ & 15;
#pragma unroll
    for (int mt = 0; mt < 2; ++mt)
#pragma unroll
        for (int nt = 0; nt < 4; ++nt)
#pragma unroll
            for (int half = 0; half < 2; ++half) {
                int t = t0 + wm*32 + mt*16 + (lane >> 2) + half*8;
                int n = wn*32 + nt*8 + (lane & 3)*2;
                size_t o = ((size_t)(b*TSEQ + t))*CEMB + h*DH + n;
                __half2 p2;
                p2.x = __float2half(acc[mt][nt][half*2]);
                p2.y = __float2half(acc[mt][nt][half*2+1]);
                *(__half2*)&g_yh[o] = p2;
            }
}

// ==================== K5: out = yh @ WpH^T + bp (R9 version) ===============
// grid(BT/128, CEMB/64). k-chunk 32, 3-stage. B natural 64n x 32k pitch40.
__global__ __launch_bounds__(256) void proj_kernel(
    const float* __restrict__ bp, float* __restrict__ out)
{
    __shared__ alignas(16) __half A[3][128*40];
    __shared__ alignas(16) __half B[3][64*40];
    const int tid = threadIdx.x, w = tid >> 5, lane = tid & 31;
    const int wm = w & 3, wn = w >> 2;
    const int m0 = blockIdx.x * 128, n0 = blockIdx.y * 64;

    float acc[2][4][4] = {};
    uint32_t aB[2], bB[2];
#pragma unroll
    for (int mt = 0; mt < 2; ++mt) {
        int ar = wm*32 + mt*16 + (lane & 15), ak = (lane >> 4) * 8;
        aB[mt] = smem_u32(&A[0][ar*40 + ak]);
    }
#pragma unroll
    for (int blk = 0; blk < 2; ++blk) {
        int br = wn*32 + blk*16 + (lane & 7) + ((lane & 16) ? 8 : 0);
        int bk = (lane & 8) ? 8 : 0;
        bB[blk] = smem_u32(&B[0][br*40 + bk]);
    }
    const int br0 = tid >> 2, bsg = (tid & 3) * 8;

    auto load_chunk = [&](int c, int stg) {
        const int k0 = c * 32;
#pragma unroll
        for (int i = 0; i < 2; ++i) {
            int idx = tid + i * 256, r = idx >> 2, sg = (idx & 3) * 8;
            cpa16(smem_u32(&A[stg][r*40 + sg]), &g_yh[(size_t)(m0 + r)*CEMB + k0 + sg]);
        }
        cpa16(smem_u32(&B[stg][br0*40 + bsg]), &g_wph[(size_t)(n0 + br0)*CEMB + k0 + bsg]);
    };

    load_chunk(0, 0); CP_COMMIT();
    load_chunk(1, 1); CP_COMMIT();
    for (int c = 0; c < 32; ++c) {
        CP_WAIT1();
        __syncthreads();
        if (c + 2 < 32) load_chunk(c + 2, (c + 2) % 3);
        CP_COMMIT();
        const uint32_t aS = (c % 3) * (uint32_t)(128*40*2);
        const uint32_t bS = (c % 3) * (uint32_t)(64*40*2);
#pragma unroll
        for (int k16 = 0; k16 < 2; ++k16) {
            uint32_t ah[2][4], bhf[2][4];
#pragma unroll
            for (int mt = 0; mt < 2; ++mt) ldsm4(ah[mt], aB[mt] + aS + k16*32);
#pragma unroll
            for (int blk = 0; blk < 2; ++blk) ldsm4(bhf[blk], bB[blk] + bS + k16*32);
#pragma unroll
            for (int mt = 0; mt < 2; ++mt)
#pragma unroll
                for (int nt = 0; nt < 4; ++nt) {
                    int blk = nt >> 1, p2 = (nt & 1) * 2;
                    mma16816(acc[mt][nt], ah[mt], bhf[blk][p2], bhf[blk][p2+1]);
                }
        }
    }
#pragma unroll
    for (int mt = 0; mt < 2; ++mt)
#pragma unroll
        for (int nt = 0; nt < 4; ++nt) {
            int n = n0 + wn*32 + nt*8 + (lane & 3)*2;
            float b0 = bp[n], b1 = bp[n + 1];
#pragma unroll
            for (int half = 0; half < 2; ++half) {
                int m = m0 + wm*32 + mt*16 + (lane >> 2) + half*8;
                size_t o = (size_t)m*CEMB + n;
                *(float2*)&out[o] = make_float2(acc[mt][nt][half*2] + b0,
                                                acc[mt][nt][half*2+1] + b1);
            }
        }
}

// ==================== launch ====================
extern "C" void kernel_launch(void* const* d_in, const int* in_sizes, int n_in,
                              void* d_out, int out_size)
{
    const float* x  = (const float*)d_in[0];
    const float* Wq = (const float*)d_in[1];
    const float* Wk = (const float*)d_in[2];
    const float* Wv = (const float*)d_in[3];
    const float* Wp = (const float*)d_in[4];
    const float* bp = (const float*)d_in[5];
    float* out = (float*)d_out;

    cvt_kernel<<<(BT*CEMB/4 + 255)/256, 256>>>(x, BT*CEMB/4, 0);
    cvtw_kernel<<<(3*NW4 + 255)/256, 256>>>(Wq, Wk, Wv);
    cvt_kernel<<<(CEMB*CEMB/4 + 255)/256, 256>>>(Wp, CEMB*CEMB/4, 2);

    qkv_kernel<<<dim3(BT/128, 24), 256>>>();
    scores_kernel<<<dim3(272, BH), 256>>>();
    zreduce_kernel<<<(BH*TSEQ + 255)/256, 256>>>();
    vscale_kernel<<<(BH*TSEQ*DH/4 + 255)/256, 256>>>();
    pv_kernel<<<dim3(16, BH), 256>>>();
    proj_kernel<<<dim3(BT/128, CEMB/64), 256>>>(bp, out);
}

// round 12
// speedup vs baseline: 1.2487x; 1.2487x over previous
#include <cuda_runtime.h>
#include <cuda_fp16.h>
#include <cstdint>
#include <cstddef>

#define HEADS 16
#define TSEQ  2048
#define CEMB  1024
#define DH    64
#define BATCH 4
#define BH    (BATCH*HEADS)   // 64
#define BT    (BATCH*TSEQ)    // 8192
#define NT2   16              // 128-row t-tiles
#define NW4   (HEADS*CEMB*DH/4)

// ---------------- scratch (device globals; allocation-free) ----------------
__device__ __align__(16) __half g_xh [(size_t)BT*CEMB];
__device__ __align__(16) __half g_wh [(size_t)3*HEADS*CEMB*DH];
__device__ __align__(16) __half g_wph[(size_t)CEMB*CEMB];
__device__ __align__(16) __half g_qh [(size_t)BH*TSEQ*DH];
__device__ __align__(16) __half g_kh [(size_t)BH*TSEQ*DH];
__device__ __align__(16) float  g_v  [(size_t)BH*TSEQ*DH];
__device__ __align__(16) __half g_vh [(size_t)BH*TSEQ*DH];
__device__ __align__(16) __half g_P  [(size_t)BH*TSEQ*TSEQ];  // 512 MiB
__device__ __align__(16) __half g_yh [(size_t)BT*CEMB];
__device__ float g_Zpart[(size_t)BH*NT2*TSEQ];
__device__ float g_Z[(size_t)BH*TSEQ];

// ---------------- helpers ----------------
__device__ __forceinline__ uint32_t smem_u32(const void* p) {
    return (uint32_t)__cvta_generic_to_shared(p);
}
__device__ __forceinline__ void cpa16(uint32_t dst, const void* src) {
    asm volatile("cp.async.cg.shared.global [%0], [%1], 16;" :: "r"(dst), "l"(src));
}
#define CP_COMMIT() asm volatile("cp.async.commit_group;" ::: "memory")
#define CP_WAIT1()  asm volatile("cp.async.wait_group 1;" ::: "memory")
#define CP_WAIT0()  asm volatile("cp.async.wait_group 0;" ::: "memory")

__device__ __forceinline__ float fast_exp(float x) {
    x = fmaxf(-60.f, fminf(60.f, x));
    float z = x * 1.4426950408889634f;
    float n = rintf(z);
    float t = (z - n) * 0.6931471805599453f;
    float p = 1.3888889e-3f;
    p = fmaf(p, t, 8.3333333e-3f);
    p = fmaf(p, t, 4.1666667e-2f);
    p = fmaf(p, t, 1.6666667e-1f);
    p = fmaf(p, t, 0.5f);
    p = fmaf(p, t, 1.0f);
    p = fmaf(p, t, 1.0f);
    return p * __int_as_float(((int)n + 127) << 23);
}
__device__ __forceinline__ void ldsm4(uint32_t r[4], uint32_t a) {
    asm volatile("ldmatrix.sync.aligned.m8n8.x4.shared.b16 {%0,%1,%2,%3},[%4];"
                 : "=r"(r[0]), "=r"(r[1]), "=r"(r[2]), "=r"(r[3]) : "r"(a));
}
__device__ __forceinline__ void ldsm4t(uint32_t r[4], uint32_t a) {
    asm volatile("ldmatrix.sync.aligned.m8n8.x4.trans.shared.b16 {%0,%1,%2,%3},[%4];"
                 : "=r"(r[0]), "=r"(r[1]), "=r"(r[2]), "=r"(r[3]) : "r"(a));
}
__device__ __forceinline__ void mma16816(float c[4], const uint32_t a[4],
                                         uint32_t b0, uint32_t b1) {
    asm volatile(
        "mma.sync.aligned.m16n8k16.row.col.f32.f16.f16.f32 "
        "{%0,%1,%2,%3},{%4,%5,%6,%7},{%8,%9},{%0,%1,%2,%3};"
        : "+f"(c[0]), "+f"(c[1]), "+f"(c[2]), "+f"(c[3])
        : "r"(a[0]), "r"(a[1]), "r"(a[2]), "r"(a[3]), "r"(b0), "r"(b1));
}

// ==================== prep kernels ====================
__global__ void cvt_kernel(const float* __restrict__ src, int n4, int sel)
{
    int i = blockIdx.x * blockDim.x + threadIdx.x;
    if (i >= n4) return;
    __half* d = (sel == 0) ? g_xh : g_wph;
    float4 v = ((const float4*)src)[i];
    __half2 a; a.x = __float2half(v.x); a.y = __float2half(v.y);
    __half2 b; b.x = __float2half(v.z); b.y = __float2half(v.w);
    ((__half2*)d)[(size_t)i * 2]     = a;
    ((__half2*)d)[(size_t)i * 2 + 1] = b;
}
__global__ void cvtw_kernel(const float* __restrict__ Wq, const float* __restrict__ Wk,
                            const float* __restrict__ Wv)
{
    int i = blockIdx.x * blockDim.x + threadIdx.x;
    if (i >= 3 * NW4) return;
    int which = i / NW4, j = i - which * NW4;
    const float* src = (which == 0) ? Wq : (which == 1) ? Wk : Wv;
    float4 v = ((const float4*)src)[j];
    __half2 a; a.x = __float2half(v.x); a.y = __float2half(v.y);
    __half2 b; b.x = __float2half(v.z); b.y = __float2half(v.w);
    ((__half2*)g_wh)[(size_t)i * 2]     = a;
    ((__half2*)g_wh)[(size_t)i * 2 + 1] = b;
}

// ==================== K1: QKV projection, 128x128 tile (R10, measured 198us) =
// grid(BT/128, 24). y: which = y/8, np = y%8 (heads np*2, np*2+1).
// k-chunk 16, 3-stage cp.async. A 128x16 pitch24; B trans 16k x 128n pitch136.
__global__ __launch_bounds__(256) void qkv_kernel()
{
    __shared__ alignas(16) __half A[3][128*24];
    __shared__ alignas(16) __half B[3][16*136];
    const int tid = threadIdx.x, w = tid >> 5, lane = tid & 31;
    const int wm = w & 3, wn = w >> 2;          // 4m x 2n warps; warp tile 32x64
    const int m0 = blockIdx.x * 128;
    const int z = blockIdx.y, which = z >> 3, np = z & 7;
    const int h0 = np * 2;
    const __half* W0 = g_wh + (size_t)(which * HEADS + h0) * CEMB * DH;

    float acc[2][8][4] = {};
    uint32_t aB[2], bB[4];
#pragma unroll
    for (int mt = 0; mt < 2; ++mt) {
        int ar = wm*32 + mt*16 + (lane & 15), ak = (lane >> 4) * 8;
        aB[mt] = smem_u32(&A[0][ar*24 + ak]);
    }
#pragma unroll
    for (int blk = 0; blk < 4; ++blk) {  // trans-B: row=k, col=n
        int br = (lane & 15), bc = wn*64 + blk*16 + ((lane & 16) ? 8 : 0);
        bB[blk] = smem_u32(&B[0][br*136 + bc]);
    }
    const int arL = tid >> 1, asL = (tid & 1) * 8;
    const int brL = tid >> 4, bsL = (tid & 15) * 8;
    const int bhead = bsL >> 6, bd = bsL & 63;
    const __half* Wsrc = W0 + (size_t)bhead * CEMB * DH;

    auto load_chunk = [&](int c, int stg) {
        const int k0 = c * 16;
        cpa16(smem_u32(&A[stg][arL*24 + asL]), &g_xh[(size_t)(m0 + arL)*CEMB + k0 + asL]);
        cpa16(smem_u32(&B[stg][brL*136 + bsL]), &Wsrc[(size_t)(k0 + brL)*DH + bd]);
    };

    load_chunk(0, 0); CP_COMMIT();
    load_chunk(1, 1); CP_COMMIT();
    for (int c = 0; c < 64; ++c) {
        CP_WAIT1();
        __syncthreads();
        if (c + 2 < 64) load_chunk(c + 2, (c + 2) % 3);
        CP_COMMIT();
        const uint32_t aS = (c % 3) * (uint32_t)(128*24*2);
        const uint32_t bS = (c % 3) * (uint32_t)(16*136*2);
        uint32_t ah[2][4], bh[4][4];
#pragma unroll
        for (int mt = 0; mt < 2; ++mt) ldsm4(ah[mt], aB[mt] + aS);
#pragma unroll
        for (int blk = 0; blk < 4; ++blk) ldsm4t(bh[blk], bB[blk] + bS);
#pragma unroll
        for (int mt = 0; mt < 2; ++mt)
#pragma unroll
            for (int nt = 0; nt < 8; ++nt) {
                int blk = nt >> 1, p2 = (nt & 1) * 2;
                mma16816(acc[mt][nt], ah[mt], bh[blk][p2], bh[blk][p2+1]);
            }
    }
#pragma unroll
    for (int mt = 0; mt < 2; ++mt)
#pragma unroll
        for (int nt = 0; nt < 8; ++nt)
#pragma unroll
            for (int half = 0; half < 2; ++half) {
                int m = m0 + wm*32 + mt*16 + (lane >> 2) + half*8;
                int n = wn*64 + nt*8 + (lane & 3)*2;
                int h = h0 + (n >> 6), d = n & 63;
                int b = m >> 11, t = m & (TSEQ - 1);
                size_t base = (((size_t)(b*HEADS + h))*TSEQ + t)*DH + d;
                float c0 = acc[mt][nt][half*2], c1 = acc[mt][nt][half*2+1];
                if (which == 2) {
                    *(float2*)&g_v[base] = make_float2(c0, c1);
                } else {
                    __half2 p2; p2.x = __float2half(c0); p2.y = __float2half(c1);
                    __half* dst = (which == 0) ? g_qh : g_kh;
                    *(__half2*)&dst[base] = p2;
                }
            }
}

// ==================== K2: scores (R9) -> P + col partials ====================
// grid(272, 64). tile 128 t-rows x 64 s-cols, causal tiles only.
__global__ __launch_bounds__(256) void scores_kernel()
{
    __shared__ alignas(16) __half A[128*72];
    __shared__ alignas(16) __half B[64*72];
    __shared__ float red[8][32];
    const int tid = threadIdx.x, w = tid >> 5, lane = tid & 31;
    const int wm = w & 3, wn = w >> 2;
    const int bh_ = blockIdx.y;
    int p = blockIdx.x;
    int tt = (int)sqrtf((float)p);
    while (tt*tt + tt > p) --tt;
    while ((tt+1)*(tt+1) + (tt+1) <= p) ++tt;
    const int ss = p - tt*tt - tt;
    const int t0 = tt * 128, s0 = ss * 64;
    const __half* qh = g_qh + (size_t)bh_*TSEQ*DH;
    const __half* kh = g_kh + (size_t)bh_*TSEQ*DH;

    float acc[2][4][4] = {};
    uint32_t aB[2], bB[2];
#pragma unroll
    for (int mt = 0; mt < 2; ++mt) {
        int ar = wm*32 + mt*16 + (lane & 15), ak = (lane >> 4) * 8;
        aB[mt] = smem_u32(&A[ar*72 + ak]);
    }
#pragma unroll
    for (int blk = 0; blk < 2; ++blk) {  // natural B: row=n(s), col=k(d)
        int br = wn*32 + blk*16 + (lane & 7) + ((lane & 16) ? 8 : 0);
        int bk = (lane & 8) ? 8 : 0;
        bB[blk] = smem_u32(&B[br*72 + bk]);
    }

#pragma unroll
    for (int i = 0; i < 4; ++i) {
        int idx = tid + i * 256, r = idx >> 3, sg = (idx & 7) * 8;
        cpa16(smem_u32(&A[r*72 + sg]), &qh[(size_t)(t0 + r)*DH + sg]);
    }
#pragma unroll
    for (int i = 0; i < 2; ++i) {
        int idx = tid + i * 256, r = idx >> 3, sg = (idx & 7) * 8;
        cpa16(smem_u32(&B[r*72 + sg]), &kh[(size_t)(s0 + r)*DH + sg]);
    }
    CP_COMMIT(); CP_WAIT0();
    __syncthreads();
#pragma unroll
    for (int k16 = 0; k16 < 4; ++k16) {
        uint32_t ah[2][4], bhf[2][4];
#pragma unroll
        for (int mt = 0; mt < 2; ++mt) ldsm4(ah[mt], aB[mt] + k16*32);
#pragma unroll
        for (int blk = 0; blk < 2; ++blk) ldsm4(bhf[blk], bB[blk] + k16*32);
#pragma unroll
        for (int mt = 0; mt < 2; ++mt)
#pragma unroll
            for (int nt = 0; nt < 4; ++nt) {
                int blk = nt >> 1, p2 = (nt & 1) * 2;
                mma16816(acc[mt][nt], ah[mt], bhf[blk][p2], bhf[blk][p2+1]);
            }
    }

    const float scale = 0.03125f;
    float cs[4][2] = {};
    size_t Pbase = (size_t)bh_ * TSEQ * TSEQ;
#pragma unroll
    for (int mt = 0; mt < 2; ++mt)
#pragma unroll
        for (int nt = 0; nt < 4; ++nt)
#pragma unroll
            for (int half = 0; half < 2; ++half) {
                int t = t0 + wm*32 + mt*16 + (lane >> 2) + half*8;
                int s = s0 + wn*32 + nt*8 + (lane & 3)*2;
                float e0 = (s     <= t) ? fast_exp(acc[mt][nt][half*2]   * scale) : 0.f;
                float e1 = (s + 1 <= t) ? fast_exp(acc[mt][nt][half*2+1] * scale) : 0.f;
                cs[nt][0] += e0; cs[nt][1] += e1;
                __half2 p2; p2.x = __float2half(e0); p2.y = __float2half(e1);
                *(__half2*)&g_P[Pbase + (size_t)t*TSEQ + s] = p2;
            }
#pragma unroll
    for (int nt = 0; nt < 4; ++nt)
#pragma unroll
        for (int par = 0; par < 2; ++par) {
            float v = cs[nt][par];
            v += __shfl_xor_sync(0xffffffffu, v, 4);
            v += __shfl_xor_sync(0xffffffffu, v, 8);
            v += __shfl_xor_sync(0xffffffffu, v, 16);
            if (lane < 4) red[w][nt*8 + (lane & 3)*2 + par] = v;
        }
    __syncthreads();
    if (tid < 64) {
        int col = tid, wh = col >> 5;
        float s = red[wh*4+0][col & 31] + red[wh*4+1][col & 31]
                + red[wh*4+2][col & 31] + red[wh*4+3][col & 31];
        g_Zpart[((size_t)bh_*NT2 + tt)*TSEQ + s0 + col] = s;
    }
}

// ==================== K3a: Z reduce (deterministic) ====================
__global__ void zreduce_kernel()
{
    int idx = blockIdx.x * blockDim.x + threadIdx.x;
    if (idx >= BH * TSEQ) return;
    int bh_ = idx >> 11, s = idx & (TSEQ - 1), ttmin = s >> 7;
    float sum = 0.f;
    for (int tt = ttmin; tt < NT2; ++tt)
        sum += g_Zpart[((size_t)bh_*NT2 + tt)*TSEQ + s];
    g_Z[idx] = sum;
}

// ==================== K3b: v/Z -> single fp16 plane ====================
__global__ void vscale_kernel()
{
    int i4 = blockIdx.x * blockDim.x + threadIdx.x;
    if (i4 >= BH * TSEQ * DH / 4) return;
    float rz = 1.0f / g_Z[i4 >> 4];
    float4 v = ((const float4*)g_v)[i4];
    __half2 a; a.x = __float2half(v.x * rz); a.y = __float2half(v.y * rz);
    __half2 b; b.x = __float2half(v.z * rz); b.y = __float2half(v.w * rz);
    ((__half2*)g_vh)[i4 * 2]     = a;
    ((__half2*)g_vh)[i4 * 2 + 1] = b;
}

// ==================== K4: y = P @ vh  (R9: 3-stage cp.async) ================
__global__ __launch_bounds__(256) void pv_kernel()
{
    __shared__ alignas(16) __half A[3][128*40];
    __shared__ alignas(16) __half B[3][32*72];
    const int tid = threadIdx.x, w = tid >> 5, lane = tid & 31;
    const int wm = w & 3, wn = w >> 2;
    const int tt = 15 - blockIdx.x;
    const int bh_ = blockIdx.y;
    const int t0 = tt * 128;
    const __half* Pp = g_P + (size_t)bh_*TSEQ*TSEQ;
    const __half* vh = g_vh + (size_t)bh_*TSEQ*DH;

    float acc[2][4][4] = {};
    uint32_t aB[2], bB[2];
#pragma unroll
    for (int mt = 0; mt < 2; ++mt) {
        int ar = wm*32 + mt*16 + (lane & 15), ak = (lane >> 4) * 8;
        aB[mt] = smem_u32(&A[0][ar*40 + ak]);
    }
#pragma unroll
    for (int blk = 0; blk < 2; ++blk) {  // trans-B: row=k(s), col=n(d)
        int br = (lane & 15), bc = wn*32 + blk*16 + ((lane & 16) ? 8 : 0);
        bB[blk] = smem_u32(&B[0][br*72 + bc]);
    }
    const int br0 = tid >> 3, bsg = (tid & 7) * 8;

    const int nsteps = 4 * (tt + 1);
    auto load_chunk = [&](int st, int stg) {
        const int s0 = st * 32;
#pragma unroll
        for (int i = 0; i < 2; ++i) {
            int idx = tid + i * 256, r = idx >> 2, sg = (idx & 3) * 8;
            cpa16(smem_u32(&A[stg][r*40 + sg]), &Pp[(size_t)(t0 + r)*TSEQ + s0 + sg]);
        }
        cpa16(smem_u32(&B[stg][br0*72 + bsg]), &vh[(size_t)(s0 + br0)*DH + bsg]);
    };

    load_chunk(0, 0); CP_COMMIT();
    if (nsteps > 1) load_chunk(1, 1);
    CP_COMMIT();
    for (int c = 0; c < nsteps; ++c) {
        CP_WAIT1();
        __syncthreads();
        if (c + 2 < nsteps) load_chunk(c + 2, (c + 2) % 3);
        CP_COMMIT();
        const uint32_t aS = (c % 3) * (uint32_t)(128*40*2);
        const uint32_t bS = (c % 3) * (uint32_t)(32*72*2);
#pragma unroll
        for (int k16 = 0; k16 < 2; ++k16) {
            uint32_t ah[2][4], bhf[2][4];
#pragma unroll
            for (int mt = 0; mt < 2; ++mt) ldsm4(ah[mt], aB[mt] + aS + k16*32);
#pragma unroll
            for (int blk = 0; blk < 2; ++blk) ldsm4t(bhf[blk], bB[blk] + bS + k16*2304);
#pragma unroll
            for (int mt = 0; mt < 2; ++mt)
#pragma unroll
                for (int nt = 0; nt < 4; ++nt) {
                    int blk = nt >> 1, p2 = (nt & 1) * 2;
                    mma16816(acc[mt][nt], ah[mt], bhf[blk][p2], bhf[blk][p2+1]);
                }
        }
    }
    const int b = bh_ >> 4, h = bh_ & 15;
#pragma unroll
    for (int mt = 0; mt < 2; ++mt)
#pragma unroll
        for (int nt = 0; nt < 4; ++nt)
#pragma unroll
            for (int half = 0; half < 2; ++half) {
                int t = t0 + wm*32 + mt*16 + (lane >> 2) + half*8;
                int n = wn*32 + nt*8 + (lane & 3)*2;
                size_t o = ((size_t)(b*TSEQ + t))*CEMB + h*DH + n;
                __half2 p2;
                p2.x = __float2half(acc[mt][nt][half*2]);
                p2.y = __float2half(acc[mt][nt][half*2+1]);
                *(__half2*)&g_yh[o] = p2;
            }
}

// ==================== K5: out = yh @ WpH^T + bp (R9: k32, 3-stage) ==========
__global__ __launch_bounds__(256) void proj_kernel(
    const float* __restrict__ bp, float* __restrict__ out)
{
    __shared__ alignas(16) __half A[3][128*40];
    __shared__ alignas(16) __half B[3][64*40];
    const int tid = threadIdx.x, w = tid >> 5, lane = tid & 31;
    const int wm = w & 3, wn = w >> 2;
    const int m0 = blockIdx.x * 128, n0 = blockIdx.y * 64;

    float acc[2][4][4] = {};
    uint32_t aB[2], bB[2];
#pragma unroll
    for (int mt = 0; mt < 2; ++mt) {
        int ar = wm*32 + mt*16 + (lane & 15), ak = (lane >> 4) * 8;
        aB[mt] = smem_u32(&A[0][ar*40 + ak]);
    }
#pragma unroll
    for (int blk = 0; blk < 2; ++blk) {  // natural B: row=n, col=k
        int br = wn*32 + blk*16 + (lane & 7) + ((lane & 16) ? 8 : 0);
        int bk = (lane & 8) ? 8 : 0;
        bB[blk] = smem_u32(&B[0][br*40 + bk]);
    }
    const int br0 = tid >> 2, bsg = (tid & 3) * 8;

    auto load_chunk = [&](int c, int stg) {
        const int k0 = c * 32;
#pragma unroll
        for (int i = 0; i < 2; ++i) {
            int idx = tid + i * 256, r = idx >> 2, sg = (idx & 3) * 8;
            cpa16(smem_u32(&A[stg][r*40 + sg]), &g_yh[(size_t)(m0 + r)*CEMB + k0 + sg]);
        }
        cpa16(smem_u32(&B[stg][br0*40 + bsg]), &g_wph[(size_t)(n0 + br0)*CEMB + k0 + bsg]);
    };

    load_chunk(0, 0); CP_COMMIT();
    load_chunk(1, 1); CP_COMMIT();
    for (int c = 0; c < 32; ++c) {
        CP_WAIT1();
        __syncthreads();
        if (c + 2 < 32) load_chunk(c + 2, (c + 2) % 3);
        CP_COMMIT();
        const uint32_t aS = (c % 3) * (uint32_t)(128*40*2);
        const uint32_t bS = (c % 3) * (uint32_t)(64*40*2);
#pragma unroll
        for (int k16 = 0; k16 < 2; ++k16) {
            uint32_t ah[2][4], bhf[2][4];
#pragma unroll
            for (int mt = 0; mt < 2; ++mt) ldsm4(ah[mt], aB[mt] + aS + k16*32);
#pragma unroll
            for (int blk = 0; blk < 2; ++blk) ldsm4(bhf[blk], bB[blk] + bS + k16*32);
#pragma unroll
            for (int mt = 0; mt < 2; ++mt)
#pragma unroll
                for (int nt = 0; nt < 4; ++nt) {
                    int blk = nt >> 1, p2 = (nt & 1) * 2;
                    mma16816(acc[mt][nt], ah[mt], bhf[blk][p2], bhf[blk][p2+1]);
                }
        }
    }
#pragma unroll
    for (int mt = 0; mt < 2; ++mt)
#pragma unroll
        for (int nt = 0; nt < 4; ++nt) {
            int n = n0 + wn*32 + nt*8 + (lane & 3)*2;
            float b0 = bp[n], b1 = bp[n + 1];
#pragma unroll
            for (int half = 0; half < 2; ++half) {
                int m = m0 + wm*32 + mt*16 + (lane >> 2) + half*8;
                size_t o = (size_t)m*CEMB + n;
                *(float2*)&out[o] = make_float2(acc[mt][nt][half*2] + b0,
                                                acc[mt][nt][half*2+1] + b1);
            }
        }
}

// ==================== launch ====================
extern "C" void kernel_launch(void* const* d_in, const int* in_sizes, int n_in,
                              void* d_out, int out_size)
{
    const float* x  = (const float*)d_in[0];
    const float* Wq = (const float*)d_in[1];
    const float* Wk = (const float*)d_in[2];
    const float* Wv = (const float*)d_in[3];
    const float* Wp = (const float*)d_in[4];
    const float* bp = (const float*)d_in[5];
    float* out = (float*)d_out;

    cvt_kernel<<<(BT*CEMB/4 + 255)/256, 256>>>(x, BT*CEMB/4, 0);
    cvtw_kernel<<<(3*NW4 + 255)/256, 256>>>(Wq, Wk, Wv);
    cvt_kernel<<<(CEMB*CEMB/4 + 255)/256, 256>>>(Wp, CEMB*CEMB/4, 2);

    qkv_kernel<<<dim3(BT/128, 24), 256>>>();
    scores_kernel<<<dim3(272, BH), 256>>>();
    zreduce_kernel<<<(BH*TSEQ + 255)/256, 256>>>();
    vscale_kernel<<<(BH*TSEQ*DH/4 + 255)/256, 256>>>();
    pv_kernel<<<dim3(16, BH), 256>>>();
    proj_kernel<<<dim3(BT/128, CEMB/64), 256>>>(bp, out);
}

// round 13
// speedup vs baseline: 1.2863x; 1.0301x over previous
#include <cuda_runtime.h>
#include <cuda_fp16.h>
#include <cstdint>
#include <cstddef>

#define HEADS 16
#define TSEQ  2048
#define CEMB  1024
#define DH    64
#define BATCH 4
#define BH    (BATCH*HEADS)   // 64
#define BT    (BATCH*TSEQ)    // 8192
#define NT2   16              // 128-row t-tiles
#define NW4   (HEADS*CEMB*DH/4)

// ---------------- scratch (device globals; allocation-free) ----------------
__device__ __align__(16) __half g_xh [(size_t)BT*CEMB];
__device__ __align__(16) __half g_wh [(size_t)3*HEADS*CEMB*DH];
__device__ __align__(16) __half g_wph[(size_t)CEMB*CEMB];
__device__ __align__(16) __half g_qh [(size_t)BH*TSEQ*DH];
__device__ __align__(16) __half g_kh [(size_t)BH*TSEQ*DH];
__device__ __align__(16) float  g_v  [(size_t)BH*TSEQ*DH];
__device__ __align__(16) __half g_vh [(size_t)BH*TSEQ*DH];
__device__ __align__(16) __half g_P  [(size_t)BH*TSEQ*TSEQ];  // 512 MiB
__device__ __align__(16) __half g_yh [(size_t)BT*CEMB];
__device__ float g_Zpart[(size_t)BH*NT2*TSEQ];
__device__ float g_Z[(size_t)BH*TSEQ];

// ---------------- helpers ----------------
__device__ __forceinline__ uint32_t smem_u32(const void* p) {
    return (uint32_t)__cvta_generic_to_shared(p);
}
__device__ __forceinline__ void cpa16(uint32_t dst, const void* src) {
    asm volatile("cp.async.cg.shared.global [%0], [%1], 16;" :: "r"(dst), "l"(src));
}
#define CP_COMMIT() asm volatile("cp.async.commit_group;" ::: "memory")
#define CP_WAIT1()  asm volatile("cp.async.wait_group 1;" ::: "memory")
#define CP_WAIT0()  asm volatile("cp.async.wait_group 0;" ::: "memory")

__device__ __forceinline__ float fast_exp(float x) {
    x = fmaxf(-60.f, fminf(60.f, x));
    float z = x * 1.4426950408889634f;
    float n = rintf(z);
    float t = (z - n) * 0.6931471805599453f;
    float p = 1.3888889e-3f;
    p = fmaf(p, t, 8.3333333e-3f);
    p = fmaf(p, t, 4.1666667e-2f);
    p = fmaf(p, t, 1.6666667e-1f);
    p = fmaf(p, t, 0.5f);
    p = fmaf(p, t, 1.0f);
    p = fmaf(p, t, 1.0f);
    return p * __int_as_float(((int)n + 127) << 23);
}
__device__ __forceinline__ void ldsm4(uint32_t r[4], uint32_t a) {
    asm volatile("ldmatrix.sync.aligned.m8n8.x4.shared.b16 {%0,%1,%2,%3},[%4];"
                 : "=r"(r[0]), "=r"(r[1]), "=r"(r[2]), "=r"(r[3]) : "r"(a));
}
__device__ __forceinline__ void ldsm4t(uint32_t r[4], uint32_t a) {
    asm volatile("ldmatrix.sync.aligned.m8n8.x4.trans.shared.b16 {%0,%1,%2,%3},[%4];"
                 : "=r"(r[0]), "=r"(r[1]), "=r"(r[2]), "=r"(r[3]) : "r"(a));
}
__device__ __forceinline__ void mma16816(float c[4], const uint32_t a[4],
                                         uint32_t b0, uint32_t b1) {
    asm volatile(
        "mma.sync.aligned.m16n8k16.row.col.f32.f16.f16.f32 "
        "{%0,%1,%2,%3},{%4,%5,%6,%7},{%8,%9},{%0,%1,%2,%3};"
        : "+f"(c[0]), "+f"(c[1]), "+f"(c[2]), "+f"(c[3])
        : "r"(a[0]), "r"(a[1]), "r"(a[2]), "r"(a[3]), "r"(b0), "r"(b1));
}

// ==================== prep kernels ====================
__global__ void cvt_kernel(const float* __restrict__ src, int n4, int sel)
{
    int i = blockIdx.x * blockDim.x + threadIdx.x;
    if (i >= n4) return;
    __half* d = (sel == 0) ? g_xh : g_wph;
    float4 v = ((const float4*)src)[i];
    __half2 a; a.x = __float2half(v.x); a.y = __float2half(v.y);
    __half2 b; b.x = __float2half(v.z); b.y = __float2half(v.w);
    ((__half2*)d)[(size_t)i * 2]     = a;
    ((__half2*)d)[(size_t)i * 2 + 1] = b;
}
__global__ void cvtw_kernel(const float* __restrict__ Wq, const float* __restrict__ Wk,
                            const float* __restrict__ Wv)
{
    int i = blockIdx.x * blockDim.x + threadIdx.x;
    if (i >= 3 * NW4) return;
    int which = i / NW4, j = i - which * NW4;
    const float* src = (which == 0) ? Wq : (which == 1) ? Wk : Wv;
    float4 v = ((const float4*)src)[j];
    __half2 a; a.x = __float2half(v.x); a.y = __float2half(v.y);
    __half2 b; b.x = __float2half(v.z); b.y = __float2half(v.w);
    ((__half2*)g_wh)[(size_t)i * 2]     = a;
    ((__half2*)g_wh)[(size_t)i * 2 + 1] = b;
}

// ==================== K1: QKV 128x128 tile, k-chunk 32, 2-stage depth-1 =====
// grid(BT/128, 24). y: which = y/8, np = y%8 (heads np*2, np*2+1).
// A 128x32 pitch40; B trans 32k x 128n pitch136.
__global__ __launch_bounds__(256) void qkv_kernel()
{
    __shared__ alignas(16) __half A[2][128*40];
    __shared__ alignas(16) __half B[2][32*136];
    const int tid = threadIdx.x, w = tid >> 5, lane = tid & 31;
    const int wm = w & 3, wn = w >> 2;          // 4m x 2n warps; warp tile 32x64
    const int m0 = blockIdx.x * 128;
    const int z = blockIdx.y, which = z >> 3, np = z & 7;
    const int h0 = np * 2;
    const __half* W0 = g_wh + (size_t)(which * HEADS + h0) * CEMB * DH;

    float acc[2][8][4] = {};
    uint32_t aB[2], bB[4];
#pragma unroll
    for (int mt = 0; mt < 2; ++mt) {
        int ar = wm*32 + mt*16 + (lane & 15), ak = (lane >> 4) * 8;
        aB[mt] = smem_u32(&A[0][ar*40 + ak]);
    }
#pragma unroll
    for (int blk = 0; blk < 4; ++blk) {  // trans-B: row=k, col=n
        int br = (lane & 15), bc = wn*64 + blk*16 + ((lane & 16) ? 8 : 0);
        bB[blk] = smem_u32(&B[0][br*136 + bc]);
    }

    auto load_chunk = [&](int c, int stg) {
        const int k0 = c * 32;
#pragma unroll
        for (int i = 0; i < 2; ++i) {
            int idx = tid + i * 256;
            {   // A: 128r x 4 segs = 512 tasks
                int r = idx >> 2, sg = (idx & 3) * 8;
                cpa16(smem_u32(&A[stg][r*40 + sg]), &g_xh[(size_t)(m0 + r)*CEMB + k0 + sg]);
            }
            {   // B: 32r x 16 segs = 512 tasks; seg covers 2 heads
                int r = idx >> 4, sg = (idx & 15) * 8;
                int hh = sg >> 6, dd = sg & 63;
                cpa16(smem_u32(&B[stg][r*136 + sg]),
                      &W0[(size_t)hh * CEMB * DH + (size_t)(k0 + r)*DH + dd]);
            }
        }
    };

    load_chunk(0, 0); CP_COMMIT();
    for (int c = 0; c < 32; ++c) {
        CP_WAIT0();
        __syncthreads();           // chunk c visible; compute(c-1) done by all
        if (c + 1 < 32) { load_chunk(c + 1, (c + 1) & 1); CP_COMMIT(); }
        const uint32_t aS = (uint32_t)(c & 1) * (128*40*2);
        const uint32_t bS = (uint32_t)(c & 1) * (32*136*2);
#pragma unroll
        for (int k16 = 0; k16 < 2; ++k16) {
            uint32_t ah[2][4], bh[4][4];
#pragma unroll
            for (int mt = 0; mt < 2; ++mt) ldsm4(ah[mt], aB[mt] + aS + k16*32);
#pragma unroll
            for (int blk = 0; blk < 4; ++blk) ldsm4t(bh[blk], bB[blk] + bS + k16*4352);
#pragma unroll
            for (int mt = 0; mt < 2; ++mt)
#pragma unroll
                for (int nt = 0; nt < 8; ++nt) {
                    int blk = nt >> 1, p2 = (nt & 1) * 2;
                    mma16816(acc[mt][nt], ah[mt], bh[blk][p2], bh[blk][p2+1]);
                }
        }
    }
#pragma unroll
    for (int mt = 0; mt < 2; ++mt)
#pragma unroll
        for (int nt = 0; nt < 8; ++nt)
#pragma unroll
            for (int half = 0; half < 2; ++half) {
                int m = m0 + wm*32 + mt*16 + (lane >> 2) + half*8;
                int n = wn*64 + nt*8 + (lane & 3)*2;
                int h = h0 + (n >> 6), d = n & 63;
                int b = m >> 11, t = m & (TSEQ - 1);
                size_t base = (((size_t)(b*HEADS + h))*TSEQ + t)*DH + d;
                float c0 = acc[mt][nt][half*2], c1 = acc[mt][nt][half*2+1];
                if (which == 2) {
                    *(float2*)&g_v[base] = make_float2(c0, c1);
                } else {
                    __half2 p2; p2.x = __float2half(c0); p2.y = __float2half(c1);
                    __half* dst = (which == 0) ? g_qh : g_kh;
                    *(__half2*)&dst[base] = p2;
                }
            }
}

// ==================== K2: scores (R9) -> P + col partials ====================
// grid(272, 64). tile 128 t-rows x 64 s-cols, causal tiles only.
__global__ __launch_bounds__(256) void scores_kernel()
{
    __shared__ alignas(16) __half A[128*72];
    __shared__ alignas(16) __half B[64*72];
    __shared__ float red[8][32];
    const int tid = threadIdx.x, w = tid >> 5, lane = tid & 31;
    const int wm = w & 3, wn = w >> 2;
    const int bh_ = blockIdx.y;
    int p = blockIdx.x;
    int tt = (int)sqrtf((float)p);
    while (tt*tt + tt > p) --tt;
    while ((tt+1)*(tt+1) + (tt+1) <= p) ++tt;
    const int ss = p - tt*tt - tt;
    const int t0 = tt * 128, s0 = ss * 64;
    const __half* qh = g_qh + (size_t)bh_*TSEQ*DH;
    const __half* kh = g_kh + (size_t)bh_*TSEQ*DH;

    float acc[2][4][4] = {};
    uint32_t aB[2], bB[2];
#pragma unroll
    for (int mt = 0; mt < 2; ++mt) {
        int ar = wm*32 + mt*16 + (lane & 15), ak = (lane >> 4) * 8;
        aB[mt] = smem_u32(&A[ar*72 + ak]);
    }
#pragma unroll
    for (int blk = 0; blk < 2; ++blk) {  // natural B: row=n(s), col=k(d)
        int br = wn*32 + blk*16 + (lane & 7) + ((lane & 16) ? 8 : 0);
        int bk = (lane & 8) ? 8 : 0;
        bB[blk] = smem_u32(&B[br*72 + bk]);
    }

#pragma unroll
    for (int i = 0; i < 4; ++i) {
        int idx = tid + i * 256, r = idx >> 3, sg = (idx & 7) * 8;
        cpa16(smem_u32(&A[r*72 + sg]), &qh[(size_t)(t0 + r)*DH + sg]);
    }
#pragma unroll
    for (int i = 0; i < 2; ++i) {
        int idx = tid + i * 256, r = idx >> 3, sg = (idx & 7) * 8;
        cpa16(smem_u32(&B[r*72 + sg]), &kh[(size_t)(s0 + r)*DH + sg]);
    }
    CP_COMMIT(); CP_WAIT0();
    __syncthreads();
#pragma unroll
    for (int k16 = 0; k16 < 4; ++k16) {
        uint32_t ah[2][4], bhf[2][4];
#pragma unroll
        for (int mt = 0; mt < 2; ++mt) ldsm4(ah[mt], aB[mt] + k16*32);
#pragma unroll
        for (int blk = 0; blk < 2; ++blk) ldsm4(bhf[blk], bB[blk] + k16*32);
#pragma unroll
        for (int mt = 0; mt < 2; ++mt)
#pragma unroll
            for (int nt = 0; nt < 4; ++nt) {
                int blk = nt >> 1, p2 = (nt & 1) * 2;
                mma16816(acc[mt][nt], ah[mt], bhf[blk][p2], bhf[blk][p2+1]);
            }
    }

    const float scale = 0.03125f;
    float cs[4][2] = {};
    size_t Pbase = (size_t)bh_ * TSEQ * TSEQ;
#pragma unroll
    for (int mt = 0; mt < 2; ++mt)
#pragma unroll
        for (int nt = 0; nt < 4; ++nt)
#pragma unroll
            for (int half = 0; half < 2; ++half) {
                int t = t0 + wm*32 + mt*16 + (lane >> 2) + half*8;
                int s = s0 + wn*32 + nt*8 + (lane & 3)*2;
                float e0 = (s     <= t) ? fast_exp(acc[mt][nt][half*2]   * scale) : 0.f;
                float e1 = (s + 1 <= t) ? fast_exp(acc[mt][nt][half*2+1] * scale) : 0.f;
                cs[nt][0] += e0; cs[nt][1] += e1;
                __half2 p2; p2.x = __float2half(e0); p2.y = __float2half(e1);
                *(__half2*)&g_P[Pbase + (size_t)t*TSEQ + s] = p2;
            }
#pragma unroll
    for (int nt = 0; nt < 4; ++nt)
#pragma unroll
        for (int par = 0; par < 2; ++par) {
            float v = cs[nt][par];
            v += __shfl_xor_sync(0xffffffffu, v, 4);
            v += __shfl_xor_sync(0xffffffffu, v, 8);
            v += __shfl_xor_sync(0xffffffffu, v, 16);
            if (lane < 4) red[w][nt*8 + (lane & 3)*2 + par] = v;
        }
    __syncthreads();
    if (tid < 64) {
        int col = tid, wh = col >> 5;
        float s = red[wh*4+0][col & 31] + red[wh*4+1][col & 31]
                + red[wh*4+2][col & 31] + red[wh*4+3][col & 31];
        g_Zpart[((size_t)bh_*NT2 + tt)*TSEQ + s0 + col] = s;
    }
}

// ==================== K3a: Z reduce (deterministic) ====================
__global__ void zreduce_kernel()
{
    int idx = blockIdx.x * blockDim.x + threadIdx.x;
    if (idx >= BH * TSEQ) return;
    int bh_ = idx >> 11, s = idx & (TSEQ - 1), ttmin = s >> 7;
    float sum = 0.f;
    for (int tt = ttmin; tt < NT2; ++tt)
        sum += g_Zpart[((size_t)bh_*NT2 + tt)*TSEQ + s];
    g_Z[idx] = sum;
}

// ==================== K3b: v/Z -> single fp16 plane ====================
__global__ void vscale_kernel()
{
    int i4 = blockIdx.x * blockDim.x + threadIdx.x;
    if (i4 >= BH * TSEQ * DH / 4) return;
    float rz = 1.0f / g_Z[i4 >> 4];
    float4 v = ((const float4*)g_v)[i4];
    __half2 a; a.x = __float2half(v.x * rz); a.y = __float2half(v.y * rz);
    __half2 b; b.x = __float2half(v.z * rz); b.y = __float2half(v.w * rz);
    ((__half2*)g_vh)[i4 * 2]     = a;
    ((__half2*)g_vh)[i4 * 2 + 1] = b;
}

// ==================== K4: y = P @ vh  (R9: 3-stage cp.async) ================
__global__ __launch_bounds__(256) void pv_kernel()
{
    __shared__ alignas(16) __half A[3][128*40];
    __shared__ alignas(16) __half B[3][32*72];
    const int tid = threadIdx.x, w = tid >> 5, lane = tid & 31;
    const int wm = w & 3, wn = w >> 2;
    const int tt = 15 - blockIdx.x;
    const int bh_ = blockIdx.y;
    const int t0 = tt * 128;
    const __half* Pp = g_P + (size_t)bh_*TSEQ*TSEQ;
    const __half* vh = g_vh + (size_t)bh_*TSEQ*DH;

    float acc[2][4][4] = {};
    uint32_t aB[2], bB[2];
#pragma unroll
    for (int mt = 0; mt < 2; ++mt) {
        int ar = wm*32 + mt*16 + (lane & 15), ak = (lane >> 4) * 8;
        aB[mt] = smem_u32(&A[0][ar*40 + ak]);
    }
#pragma unroll
    for (int blk = 0; blk < 2; ++blk) {  // trans-B: row=k(s), col=n(d)
        int br = (lane & 15), bc = wn*32 + blk*16 + ((lane & 16) ? 8 : 0);
        bB[blk] = smem_u32(&B[0][br*72 + bc]);
    }
    const int br0 = tid >> 3, bsg = (tid & 7) * 8;

    const int nsteps = 4 * (tt + 1);
    auto load_chunk = [&](int st, int stg) {
        const int s0 = st * 32;
#pragma unroll
        for (int i = 0; i < 2; ++i) {
            int idx = tid + i * 256, r = idx >> 2, sg = (idx & 3) * 8;
            cpa16(smem_u32(&A[stg][r*40 + sg]), &Pp[(size_t)(t0 + r)*TSEQ + s0 + sg]);
        }
        cpa16(smem_u32(&B[stg][br0*72 + bsg]), &vh[(size_t)(s0 + br0)*DH + bsg]);
    };

    load_chunk(0, 0); CP_COMMIT();
    if (nsteps > 1) load_chunk(1, 1);
    CP_COMMIT();
    for (int c = 0; c < nsteps; ++c) {
        CP_WAIT1();
        __syncthreads();
        if (c + 2 < nsteps) load_chunk(c + 2, (c + 2) % 3);
        CP_COMMIT();
        const uint32_t aS = (c % 3) * (uint32_t)(128*40*2);
        const uint32_t bS = (c % 3) * (uint32_t)(32*72*2);
#pragma unroll
        for (int k16 = 0; k16 < 2; ++k16) {
            uint32_t ah[2][4], bhf[2][4];
#pragma unroll
            for (int mt = 0; mt < 2; ++mt) ldsm4(ah[mt], aB[mt] + aS + k16*32);
#pragma unroll
            for (int blk = 0; blk < 2; ++blk) ldsm4t(bhf[blk], bB[blk] + bS + k16*2304);
#pragma unroll
            for (int mt = 0; mt < 2; ++mt)
#pragma unroll
                for (int nt = 0; nt < 4; ++nt) {
                    int blk = nt >> 1, p2 = (nt & 1) * 2;
                    mma16816(acc[mt][nt], ah[mt], bhf[blk][p2], bhf[blk][p2+1]);
                }
        }
    }
    const int b = bh_ >> 4, h = bh_ & 15;
#pragma unroll
    for (int mt = 0; mt < 2; ++mt)
#pragma unroll
        for (int nt = 0; nt < 4; ++nt)
#pragma unroll
            for (int half = 0; half < 2; ++half) {
                int t = t0 + wm*32 + mt*16 + (lane >> 2) + half*8;
                int n = wn*32 + nt*8 + (lane & 3)*2;
                size_t o = ((size_t)(b*TSEQ + t))*CEMB + h*DH + n;
                __half2 p2;
                p2.x = __float2half(acc[mt][nt][half*2]);
                p2.y = __float2half(acc[mt][nt][half*2+1]);
                *(__half2*)&g_yh[o] = p2;
            }
}

// ==================== K5: proj 128x128 tile, k32, 2-stage depth-1 ===========
// grid(BT/128, CEMB/128). B natural 128n x 32k pitch40.
__global__ __launch_bounds__(256) void proj_kernel(
    const float* __restrict__ bp, float* __restrict__ out)
{
    __shared__ alignas(16) __half A[2][128*40];
    __shared__ alignas(16) __half B[2][128*40];
    const int tid = threadIdx.x, w = tid >> 5, lane = tid & 31;
    const int wm = w & 3, wn = w >> 2;          // warp tile 32m x 64n
    const int m0 = blockIdx.x * 128, n0 = blockIdx.y * 128;

    float acc[2][8][4] = {};
    uint32_t aB[2], bB[4];
#pragma unroll
    for (int mt = 0; mt < 2; ++mt) {
        int ar = wm*32 + mt*16 + (lane & 15), ak = (lane >> 4) * 8;
        aB[mt] = smem_u32(&A[0][ar*40 + ak]);
    }
#pragma unroll
    for (int blk = 0; blk < 4; ++blk) {  // natural B: row=n, col=k
        int br = wn*64 + blk*16 + (lane & 7) + ((lane & 16) ? 8 : 0);
        int bk = (lane & 8) ? 8 : 0;
        bB[blk] = smem_u32(&B[0][br*40 + bk]);
    }

    auto load_chunk = [&](int c, int stg) {
        const int k0 = c * 32;
#pragma unroll
        for (int i = 0; i < 2; ++i) {
            int idx = tid + i * 256, r = idx >> 2, sg = (idx & 3) * 8;
            cpa16(smem_u32(&A[stg][r*40 + sg]), &g_yh[(size_t)(m0 + r)*CEMB + k0 + sg]);
            cpa16(smem_u32(&B[stg][r*40 + sg]), &g_wph[(size_t)(n0 + r)*CEMB + k0 + sg]);
        }
    };

    load_chunk(0, 0); CP_COMMIT();
    for (int c = 0; c < 32; ++c) {
        CP_WAIT0();
        __syncthreads();
        if (c + 1 < 32) { load_chunk(c + 1, (c + 1) & 1); CP_COMMIT(); }
        const uint32_t aS = (uint32_t)(c & 1) * (128*40*2);
#pragma unroll
        for (int k16 = 0; k16 < 2; ++k16) {
            uint32_t ah[2][4], bhf[4][4];
#pragma unroll
            for (int mt = 0; mt < 2; ++mt) ldsm4(ah[mt], aB[mt] + aS + k16*32);
#pragma unroll
            for (int blk = 0; blk < 4; ++blk) ldsm4(bhf[blk], bB[blk] + aS + k16*32);
#pragma unroll
            for (int mt = 0; mt < 2; ++mt)
#pragma unroll
                for (int nt = 0; nt < 8; ++nt) {
                    int blk = nt >> 1, p2 = (nt & 1) * 2;
                    mma16816(acc[mt][nt], ah[mt], bhf[blk][p2], bhf[blk][p2+1]);
                }
        }
    }
#pragma unroll
    for (int mt = 0; mt < 2; ++mt)
#pragma unroll
        for (int nt = 0; nt < 8; ++nt) {
            int n = n0 + wn*64 + nt*8 + (lane & 3)*2;
            float b0 = bp[n], b1 = bp[n + 1];
#pragma unroll
            for (int half = 0; half < 2; ++half) {
                int m = m0 + wm*32 + mt*16 + (lane >> 2) + half*8;
                size_t o = (size_t)m*CEMB + n;
                *(float2*)&out[o] = make_float2(acc[mt][nt][half*2] + b0,
                                                acc[mt][nt][half*2+1] + b1);
            }
        }
}

// ==================== launch ====================
extern "C" void kernel_launch(void* const* d_in, const int* in_sizes, int n_in,
                              void* d_out, int out_size)
{
    const float* x  = (const float*)d_in[0];
    const float* Wq = (const float*)d_in[1];
    const float* Wk = (const float*)d_in[2];
    const float* Wv = (const float*)d_in[3];
    const float* Wp = (const float*)d_in[4];
    const float* bp = (const float*)d_in[5];
    float* out = (float*)d_out;

    cvt_kernel<<<(BT*CEMB/4 + 255)/256, 256>>>(x, BT*CEMB/4, 0);
    cvtw_kernel<<<(3*NW4 + 255)/256, 256>>>(Wq, Wk, Wv);
    cvt_kernel<<<(CEMB*CEMB/4 + 255)/256, 256>>>(Wp, CEMB*CEMB/4, 2);

    qkv_kernel<<<dim3(BT/128, 24), 256>>>();
    scores_kernel<<<dim3(272, BH), 256>>>();
    zreduce_kernel<<<(BH*TSEQ + 255)/256, 256>>>();
    vscale_kernel<<<(BH*TSEQ*DH/4 + 255)/256, 256>>>();
    pv_kernel<<<dim3(16, BH), 256>>>();
    proj_kernel<<<dim3(BT/128, CEMB/128), 256>>>(bp, out);
}

// round 16
// speedup vs baseline: 1.2911x; 1.0037x over previous
#include <cuda_runtime.h>
#include <cuda_fp16.h>
#include <cstdint>
#include <cstddef>

#define HEADS 16
#define TSEQ  2048
#define CEMB  1024
#define DH    64
#define BATCH 4
#define BH    (BATCH*HEADS)   // 64
#define BT    (BATCH*TSEQ)    // 8192
#define NT2   16              // 128-row t-tiles
#define NW4   (HEADS*CEMB*DH/4)

// qkv dynamic smem layout (halves)
#define QKV_ASTG (128*72)
#define QKV_BSTG (64*136)
#define QKV_STG_BYTES ((QKV_ASTG + QKV_BSTG) * 2)   // 35840
#define QKV_SMEM (2 * QKV_STG_BYTES)                // 71680

// ---------------- scratch (device globals; allocation-free) ----------------
__device__ __align__(16) __half g_xh [(size_t)BT*CEMB];
__device__ __align__(16) __half g_wh [(size_t)3*HEADS*CEMB*DH];
__device__ __align__(16) __half g_wph[(size_t)CEMB*CEMB];
__device__ __align__(16) __half g_qh [(size_t)BH*TSEQ*DH];
__device__ __align__(16) __half g_kh [(size_t)BH*TSEQ*DH];
__device__ __align__(16) float  g_v  [(size_t)BH*TSEQ*DH];
__device__ __align__(16) __half g_vh [(size_t)BH*TSEQ*DH];
__device__ __align__(16) __half g_P  [(size_t)BH*TSEQ*TSEQ];  // 512 MiB
__device__ __align__(16) __half g_yh [(size_t)BT*CEMB];
__device__ float g_Zpart[(size_t)BH*NT2*TSEQ];
__device__ float g_Z[(size_t)BH*TSEQ];

// ---------------- helpers ----------------
__device__ __forceinline__ uint32_t smem_u32(const void* p) {
    return (uint32_t)__cvta_generic_to_shared(p);
}
__device__ __forceinline__ void cpa16(uint32_t dst, const void* src) {
    asm volatile("cp.async.cg.shared.global [%0], [%1], 16;" :: "r"(dst), "l"(src));
}
#define CP_COMMIT() asm volatile("cp.async.commit_group;" ::: "memory")
#define CP_WAIT1()  asm volatile("cp.async.wait_group 1;" ::: "memory")
#define CP_WAIT0()  asm volatile("cp.async.wait_group 0;" ::: "memory")

__device__ __forceinline__ float fast_exp(float x) {
    x = fmaxf(-60.f, fminf(60.f, x));
    float z = x * 1.4426950408889634f;
    float n = rintf(z);
    float t = (z - n) * 0.6931471805599453f;
    float p = 1.3888889e-3f;
    p = fmaf(p, t, 8.3333333e-3f);
    p = fmaf(p, t, 4.1666667e-2f);
    p = fmaf(p, t, 1.6666667e-1f);
    p = fmaf(p, t, 0.5f);
    p = fmaf(p, t, 1.0f);
    p = fmaf(p, t, 1.0f);
    return p * __int_as_float(((int)n + 127) << 23);
}
__device__ __forceinline__ void ldsm4(uint32_t r[4], uint32_t a) {
    asm volatile("ldmatrix.sync.aligned.m8n8.x4.shared.b16 {%0,%1,%2,%3},[%4];"
                 : "=r"(r[0]), "=r"(r[1]), "=r"(r[2]), "=r"(r[3]) : "r"(a));
}
__device__ __forceinline__ void ldsm4t(uint32_t r[4], uint32_t a) {
    asm volatile("ldmatrix.sync.aligned.m8n8.x4.trans.shared.b16 {%0,%1,%2,%3},[%4];"
                 : "=r"(r[0]), "=r"(r[1]), "=r"(r[2]), "=r"(r[3]) : "r"(a));
}
__device__ __forceinline__ void mma16816(float c[4], const uint32_t a[4],
                                         uint32_t b0, uint32_t b1) {
    asm volatile(
        "mma.sync.aligned.m16n8k16.row.col.f32.f16.f16.f32 "
        "{%0,%1,%2,%3},{%4,%5,%6,%7},{%8,%9},{%0,%1,%2,%3};"
        : "+f"(c[0]), "+f"(c[1]), "+f"(c[2]), "+f"(c[3])
        : "r"(a[0]), "r"(a[1]), "r"(a[2]), "r"(a[3]), "r"(b0), "r"(b1));
}

// ==================== prep kernels ====================
__global__ void cvt_kernel(const float* __restrict__ src, int n4, int sel)
{
    int i = blockIdx.x * blockDim.x + threadIdx.x;
    if (i >= n4) return;
    __half* d = (sel == 0) ? g_xh : g_wph;
    float4 v = ((const float4*)src)[i];
    __half2 a; a.x = __float2half(v.x); a.y = __float2half(v.y);
    __half2 b; b.x = __float2half(v.z); b.y = __float2half(v.w);
    ((__half2*)d)[(size_t)i * 2]     = a;
    ((__half2*)d)[(size_t)i * 2 + 1] = b;
}
__global__ void cvtw_kernel(const float* __restrict__ Wq, const float* __restrict__ Wk,
                            const float* __restrict__ Wv)
{
    int i = blockIdx.x * blockDim.x + threadIdx.x;
    if (i >= 3 * NW4) return;
    int which = i / NW4, j = i - which * NW4;
    const float* src = (which == 0) ? Wq : (which == 1) ? Wk : Wv;
    float4 v = ((const float4*)src)[j];
    __half2 a; a.x = __float2half(v.x); a.y = __float2half(v.y);
    __half2 b; b.x = __float2half(v.z); b.y = __float2half(v.w);
    ((__half2*)g_wh)[(size_t)i * 2]     = a;
    ((__half2*)g_wh)[(size_t)i * 2 + 1] = b;
}

// ==================== K1: QKV 128x128 tile, k-chunk 64, 2-stage =============
// grid(BT/128, 24). y: which = y/8, np = y%8 (heads np*2, np*2+1).
// Dynamic smem: per stage A 128x64 pitch72 + B trans 64k x 128n pitch136.
__global__ __launch_bounds__(256) void qkv_kernel()
{
    extern __shared__ __align__(16) __half sm[];
    const int tid = threadIdx.x, w = tid >> 5, lane = tid & 31;
    const int wm = w & 3, wn = w >> 2;          // 4m x 2n warps; warp tile 32x64
    const int m0 = blockIdx.x * 128;
    const int z = blockIdx.y, which = z >> 3, np = z & 7;
    const int h0 = np * 2;
    const __half* W0 = g_wh + (size_t)(which * HEADS + h0) * CEMB * DH;

    __half* A0 = sm;
    __half* B0 = sm + QKV_ASTG;

    float acc[2][8][4] = {};
    uint32_t aB[2], bB[4];
#pragma unroll
    for (int mt = 0; mt < 2; ++mt) {
        int ar = wm*32 + mt*16 + (lane & 15), ak = (lane >> 4) * 8;
        aB[mt] = smem_u32(&A0[ar*72 + ak]);
    }
#pragma unroll
    for (int blk = 0; blk < 4; ++blk) {  // trans-B: row=k, col=n
        int br = (lane & 15), bc = wn*64 + blk*16 + ((lane & 16) ? 8 : 0);
        bB[blk] = smem_u32(&B0[br*136 + bc]);
    }

    auto load_chunk = [&](int c, int stg) {
        const int k0 = c * 64;
        __half* As = sm + (size_t)stg * (QKV_ASTG + QKV_BSTG);
        __half* Bs = As + QKV_ASTG;
#pragma unroll
        for (int i = 0; i < 4; ++i) {
            int idx = tid + i * 256;
            {   // A: 128r x 8 segs = 1024 tasks
                int r = idx >> 3, sg = (idx & 7) * 8;
                cpa16(smem_u32(&As[r*72 + sg]), &g_xh[(size_t)(m0 + r)*CEMB + k0 + sg]);
            }
            {   // B: 64r x 16 segs = 1024 tasks; seg covers 2 heads
                int r = idx >> 4, sg = (idx & 15) * 8;
                int hh = sg >> 6, dd = sg & 63;
                cpa16(smem_u32(&Bs[r*136 + sg]),
                      &W0[(size_t)hh * CEMB * DH + (size_t)(k0 + r)*DH + dd]);
            }
        }
    };

    load_chunk(0, 0); CP_COMMIT();
    for (int c = 0; c < 16; ++c) {
        CP_WAIT0();
        __syncthreads();           // chunk c visible; compute(c-1) done by all
        if (c + 1 < 16) { load_chunk(c + 1, (c + 1) & 1); CP_COMMIT(); }
        const uint32_t stS = (uint32_t)(c & 1) * QKV_STG_BYTES;
#pragma unroll
        for (int k16 = 0; k16 < 4; ++k16) {
            uint32_t ah[2][4], bh[4][4];
#pragma unroll
            for (int mt = 0; mt < 2; ++mt) ldsm4(ah[mt], aB[mt] + stS + k16*32);
#pragma unroll
            for (int blk = 0; blk < 4; ++blk) ldsm4t(bh[blk], bB[blk] + stS + k16*4352);
#pragma unroll
            for (int mt = 0; mt < 2; ++mt)
#pragma unroll
                for (int nt = 0; nt < 8; ++nt) {
                    int blk = nt >> 1, p2 = (nt & 1) * 2;
                    mma16816(acc[mt][nt], ah[mt], bh[blk][p2], bh[blk][p2+1]);
                }
        }
    }
#pragma unroll
    for (int mt = 0; mt < 2; ++mt)
#pragma unroll
        for (int nt = 0; nt < 8; ++nt)
#pragma unroll
            for (int half = 0; half < 2; ++half) {
                int m = m0 + wm*32 + mt*16 + (lane >> 2) + half*8;
                int n = wn*64 + nt*8 + (lane & 3)*2;
                int h = h0 + (n >> 6), d = n & 63;
                int b = m >> 11, t = m & (TSEQ - 1);
                size_t base = (((size_t)(b*HEADS + h))*TSEQ + t)*DH + d;
                float c0 = acc[mt][nt][half*2], c1 = acc[mt][nt][half*2+1];
                if (which == 2) {
                    *(float2*)&g_v[base] = make_float2(c0, c1);
                } else {
                    __half2 p2; p2.x = __float2half(c0); p2.y = __float2half(c1);
                    __half* dst = (which == 0) ? g_qh : g_kh;
                    *(__half2*)&dst[base] = p2;
                }
            }
}

// ==================== K2: scores (R9) -> P + col partials ====================
// grid(272, 64). tile 128 t-rows x 64 s-cols, causal tiles only.
__global__ __launch_bounds__(256) void scores_kernel()
{
    __shared__ alignas(16) __half A[128*72];
    __shared__ alignas(16) __half B[64*72];
    __shared__ float red[8][32];
    const int tid = threadIdx.x, w = tid >> 5, lane = tid & 31;
    const int wm = w & 3, wn = w >> 2;
    const int bh_ = blockIdx.y;
    int p = blockIdx.x;
    int tt = (int)sqrtf((float)p);
    while (tt*tt + tt > p) --tt;
    while ((tt+1)*(tt+1) + (tt+1) <= p) ++tt;
    const int ss = p - tt*tt - tt;
    const int t0 = tt * 128, s0 = ss * 64;
    const __half* qh = g_qh + (size_t)bh_*TSEQ*DH;
    const __half* kh = g_kh + (size_t)bh_*TSEQ*DH;

    float acc[2][4][4] = {};
    uint32_t aB[2], bB[2];
#pragma unroll
    for (int mt = 0; mt < 2; ++mt) {
        int ar = wm*32 + mt*16 + (lane & 15), ak = (lane >> 4) * 8;
        aB[mt] = smem_u32(&A[ar*72 + ak]);
    }
#pragma unroll
    for (int blk = 0; blk < 2; ++blk) {  // natural B: row=n(s), col=k(d)
        int br = wn*32 + blk*16 + (lane & 7) + ((lane & 16) ? 8 : 0);
        int bk = (lane & 8) ? 8 : 0;
        bB[blk] = smem_u32(&B[br*72 + bk]);
    }

#pragma unroll
    for (int i = 0; i < 4; ++i) {
        int idx = tid + i * 256, r = idx >> 3, sg = (idx & 7) * 8;
        cpa16(smem_u32(&A[r*72 + sg]), &qh[(size_t)(t0 + r)*DH + sg]);
    }
#pragma unroll
    for (int i = 0; i < 2; ++i) {
        int idx = tid + i * 256, r = idx >> 3, sg = (idx & 7) * 8;
        cpa16(smem_u32(&B[r*72 + sg]), &kh[(size_t)(s0 + r)*DH + sg]);
    }
    CP_COMMIT(); CP_WAIT0();
    __syncthreads();
#pragma unroll
    for (int k16 = 0; k16 < 4; ++k16) {
        uint32_t ah[2][4], bhf[2][4];
#pragma unroll
        for (int mt = 0; mt < 2; ++mt) ldsm4(ah[mt], aB[mt] + k16*32);
#pragma unroll
        for (int blk = 0; blk < 2; ++blk) ldsm4(bhf[blk], bB[blk] + k16*32);
#pragma unroll
        for (int mt = 0; mt < 2; ++mt)
#pragma unroll
            for (int nt = 0; nt < 4; ++nt) {
                int blk = nt >> 1, p2 = (nt & 1) * 2;
                mma16816(acc[mt][nt], ah[mt], bhf[blk][p2], bhf[blk][p2+1]);
            }
    }

    const float scale = 0.03125f;
    float cs[4][2] = {};
    size_t Pbase = (size_t)bh_ * TSEQ * TSEQ;
#pragma unroll
    for (int mt = 0; mt < 2; ++mt)
#pragma unroll
        for (int nt = 0; nt < 4; ++nt)
#pragma unroll
            for (int half = 0; half < 2; ++half) {
                int t = t0 + wm*32 + mt*16 + (lane >> 2) + half*8;
                int s = s0 + wn*32 + nt*8 + (lane & 3)*2;
                float e0 = (s     <= t) ? fast_exp(acc[mt][nt][half*2]   * scale) : 0.f;
                float e1 = (s + 1 <= t) ? fast_exp(acc[mt][nt][half*2+1] * scale) : 0.f;
                cs[nt][0] += e0; cs[nt][1] += e1;
                __half2 p2; p2.x = __float2half(e0); p2.y = __float2half(e1);
                *(__half2*)&g_P[Pbase + (size_t)t*TSEQ + s] = p2;
            }
#pragma unroll
    for (int nt = 0; nt < 4; ++nt)
#pragma unroll
        for (int par = 0; par < 2; ++par) {
            float v = cs[nt][par];
            v += __shfl_xor_sync(0xffffffffu, v, 4);
            v += __shfl_xor_sync(0xffffffffu, v, 8);
            v += __shfl_xor_sync(0xffffffffu, v, 16);
            if (lane < 4) red[w][nt*8 + (lane & 3)*2 + par] = v;
        }
    __syncthreads();
    if (tid < 64) {
        int col = tid, wh = col >> 5;
        float s = red[wh*4+0][col & 31] + red[wh*4+1][col & 31]
                + red[wh*4+2][col & 31] + red[wh*4+3][col & 31];
        g_Zpart[((size_t)bh_*NT2 + tt)*TSEQ + s0 + col] = s;
    }
}

// ==================== K3a: Z reduce (deterministic) ====================
__global__ void zreduce_kernel()
{
    int idx = blockIdx.x * blockDim.x + threadIdx.x;
    if (idx >= BH * TSEQ) return;
    int bh_ = idx >> 11, s = idx & (TSEQ - 1), ttmin = s >> 7;
    float sum = 0.f;
    for (int tt = ttmin; tt < NT2; ++tt)
        sum += g_Zpart[((size_t)bh_*NT2 + tt)*TSEQ + s];
    g_Z[idx] = sum;
}

// ==================== K3b: v/Z -> single fp16 plane ====================
__global__ void vscale_kernel()
{
    int i4 = blockIdx.x * blockDim.x + threadIdx.x;
    if (i4 >= BH * TSEQ * DH / 4) return;
    float rz = 1.0f / g_Z[i4 >> 4];
    float4 v = ((const float4*)g_v)[i4];
    __half2 a; a.x = __float2half(v.x * rz); a.y = __float2half(v.y * rz);
    __half2 b; b.x = __float2half(v.z * rz); b.y = __float2half(v.w * rz);
    ((__half2*)g_vh)[i4 * 2]     = a;
    ((__half2*)g_vh)[i4 * 2 + 1] = b;
}

// ==================== K4: y = P @ vh  (R9: 3-stage cp.async) ================
__global__ __launch_bounds__(256) void pv_kernel()
{
    __shared__ alignas(16) __half A[3][128*40];
    __shared__ alignas(16) __half B[3][32*72];
    const int tid = threadIdx.x, w = tid >> 5, lane = tid & 31;
    const int wm = w & 3, wn = w >> 2;
    const int tt = 15 - blockIdx.x;
    const int bh_ = blockIdx.y;
    const int t0 = tt * 128;
    const __half* Pp = g_P + (size_t)bh_*TSEQ*TSEQ;
    const __half* vh = g_vh + (size_t)bh_*TSEQ*DH;

    float acc[2][4][4] = {};
    uint32_t aB[2], bB[2];
#pragma unroll
    for (int mt = 0; mt < 2; ++mt) {
        int ar = wm*32 + mt*16 + (lane & 15), ak = (lane >> 4) * 8;
        aB[mt] = smem_u32(&A[0][ar*40 + ak]);
    }
#pragma unroll
    for (int blk = 0; blk < 2; ++blk) {  // trans-B: row=k(s), col=n(d)
        int br = (lane & 15), bc = wn*32 + blk*16 + ((lane & 16) ? 8 : 0);
        bB[blk] = smem_u32(&B[0][br*72 + bc]);
    }
    const int br0 = tid >> 3, bsg = (tid & 7) * 8;

    const int nsteps = 4 * (tt + 1);
    auto load_chunk = [&](int st, int stg) {
        const int s0 = st * 32;
#pragma unroll
        for (int i = 0; i < 2; ++i) {
            int idx = tid + i * 256, r = idx >> 2, sg = (idx & 3) * 8;
            cpa16(smem_u32(&A[stg][r*40 + sg]), &Pp[(size_t)(t0 + r)*TSEQ + s0 + sg]);
        }
        cpa16(smem_u32(&B[stg][br0*72 + bsg]), &vh[(size_t)(s0 + br0)*DH + bsg]);
    };

    load_chunk(0, 0); CP_COMMIT();
    if (nsteps > 1) load_chunk(1, 1);
    CP_COMMIT();
    for (int c = 0; c < nsteps; ++c) {
        CP_WAIT1();
        __syncthreads();
        if (c + 2 < nsteps) load_chunk(c + 2, (c + 2) % 3);
        CP_COMMIT();
        const uint32_t aS = (c % 3) * (uint32_t)(128*40*2);
        const uint32_t bS = (c % 3) * (uint32_t)(32*72*2);
#pragma unroll
        for (int k16 = 0; k16 < 2; ++k16) {
            uint32_t ah[2][4], bhf[2][4];
#pragma unroll
            for (int mt = 0; mt < 2; ++mt) ldsm4(ah[mt], aB[mt] + aS + k16*32);
#pragma unroll
            for (int blk = 0; blk < 2; ++blk) ldsm4t(bhf[blk], bB[blk] + bS + k16*2304);
#pragma unroll
            for (int mt = 0; mt < 2; ++mt)
#pragma unroll
                for (int nt = 0; nt < 4; ++nt) {
                    int blk = nt >> 1, p2 = (nt & 1) * 2;
                    mma16816(acc[mt][nt], ah[mt], bhf[blk][p2], bhf[blk][p2+1]);
                }
        }
    }
    const int b = bh_ >> 4, h = bh_ & 15;
#pragma unroll
    for (int mt = 0; mt < 2; ++mt)
#pragma unroll
        for (int nt = 0; nt < 4; ++nt)
#pragma unroll
            for (int half = 0; half < 2; ++half) {
                int t = t0 + wm*32 + mt*16 + (lane >> 2) + half*8;
                int n = wn*32 + nt*8 + (lane & 3)*2;
                size_t o = ((size_t)(b*TSEQ + t))*CEMB + h*DH + n;
                __half2 p2;
                p2.x = __float2half(acc[mt][nt][half*2]);
                p2.y = __float2half(acc[mt][nt][half*2+1]);
                *(__half2*)&g_yh[o] = p2;
            }
}

// ==================== K5: proj 128x128 tile, k32, 2-stage depth-1 ===========
// grid(BT/128, CEMB/128). B natural 128n x 32k pitch40.
__global__ __launch_bounds__(256) void proj_kernel(
    const float* __restrict__ bp, float* __restrict__ out)
{
    __shared__ alignas(16) __half A[2][128*40];
    __shared__ alignas(16) __half B[2][128*40];
    const int tid = threadIdx.x, w = tid >> 5, lane = tid & 31;
    const int wm = w & 3, wn = w >> 2;          // warp tile 32m x 64n
    const int m0 = blockIdx.x * 128, n0 = blockIdx.y * 128;

    float acc[2][8][4] = {};
    uint32_t aB[2], bB[4];
#pragma unroll
    for (int mt = 0; mt < 2; ++mt) {
        int ar = wm*32 + mt*16 + (lane & 15), ak = (lane >> 4) * 8;
        aB[mt] = smem_u32(&A[0][ar*40 + ak]);
    }
#pragma unroll
    for (int blk = 0; blk < 4; ++blk) {  // natural B: row=n, col=k
        int br = wn*64 + blk*16 + (lane & 7) + ((lane & 16) ? 8 : 0);
        int bk = (lane & 8) ? 8 : 0;
        bB[blk] = smem_u32(&B[0][br*40 + bk]);
    }

    auto load_chunk = [&](int c, int stg) {
        const int k0 = c * 32;
#pragma unroll
        for (int i = 0; i < 2; ++i) {
            int idx = tid + i * 256, r = idx >> 2, sg = (idx & 3) * 8;
            cpa16(smem_u32(&A[stg][r*40 + sg]), &g_yh[(size_t)(m0 + r)*CEMB + k0 + sg]);
            cpa16(smem_u32(&B[stg][r*40 + sg]), &g_wph[(size_t)(n0 + r)*CEMB + k0 + sg]);
        }
    };

    load_chunk(0, 0); CP_COMMIT();
    for (int c = 0; c < 32; ++c) {
        CP_WAIT0();
        __syncthreads();
        if (c + 1 < 32) { load_chunk(c + 1, (c + 1) & 1); CP_COMMIT(); }
        const uint32_t aS = (uint32_t)(c & 1) * (128*40*2);
#pragma unroll
        for (int k16 = 0; k16 < 2; ++k16) {
            uint32_t ah[2][4], bhf[4][4];
#pragma unroll
            for (int mt = 0; mt < 2; ++mt) ldsm4(ah[mt], aB[mt] + aS + k16*32);
#pragma unroll
            for (int blk = 0; blk < 4; ++blk) ldsm4(bhf[blk], bB[blk] + aS + k16*32);
#pragma unroll
            for (int mt = 0; mt < 2; ++mt)
#pragma unroll
                for (int nt = 0; nt < 8; ++nt) {
                    int blk = nt >> 1, p2 = (nt & 1) * 2;
                    mma16816(acc[mt][nt], ah[mt], bhf[blk][p2], bhf[blk][p2+1]);
                }
        }
    }
#pragma unroll
    for (int mt = 0; mt < 2; ++mt)
#pragma unroll
        for (int nt = 0; nt < 8; ++nt) {
            int n = n0 + wn*64 + nt*8 + (lane & 3)*2;
            float b0 = bp[n], b1 = bp[n + 1];
#pragma unroll
            for (int half = 0; half < 2; ++half) {
                int m = m0 + wm*32 + mt*16 + (lane >> 2) + half*8;
                size_t o = (size_t)m*CEMB + n;
                *(float2*)&out[o] = make_float2(acc[mt][nt][half*2] + b0,
                                                acc[mt][nt][half*2+1] + b1);
            }
        }
}

// ==================== launch ====================
extern "C" void kernel_launch(void* const* d_in, const int* in_sizes, int n_in,
                              void* d_out, int out_size)
{
    const float* x  = (const float*)d_in[0];
    const float* Wq = (const float*)d_in[1];
    const float* Wk = (const float*)d_in[2];
    const float* Wv = (const float*)d_in[3];
    const float* Wp = (const float*)d_in[4];
    const float* bp = (const float*)d_in[5];
    float* out = (float*)d_out;

    // host-side attribute (not a stream op; graph-capture safe; idempotent)
    cudaFuncSetAttribute(qkv_kernel,
                         cudaFuncAttributeMaxDynamicSharedMemorySize, QKV_SMEM);

    cvt_kernel<<<(BT*CEMB/4 + 255)/256, 256>>>(x, BT*CEMB/4, 0);
    cvtw_kernel<<<(3*NW4 + 255)/256, 256>>>(Wq, Wk, Wv);
    cvt_kernel<<<(CEMB*CEMB/4 + 255)/256, 256>>>(Wp, CEMB*CEMB/4, 2);

    qkv_kernel<<<dim3(BT/128, 24), 256, QKV_SMEM>>>();
    scores_kernel<<<dim3(272, BH), 256>>>();
    zreduce_kernel<<<(BH*TSEQ + 255)/256, 256>>>();
    vscale_kernel<<<(BH*TSEQ*DH/4 + 255)/256, 256>>>();
    pv_kernel<<<dim3(16, BH), 256>>>();
    proj_kernel<<<dim3(BT/128, CEMB/128), 256>>>(bp, out);
}

// round 17
// speedup vs baseline: 1.3234x; 1.0250x over previous
#include <cuda_runtime.h>
#include <cuda_fp16.h>
#include <cstdint>
#include <cstddef>

#define HEADS 16
#define TSEQ  2048
#define CEMB  1024
#define DH    64
#define BATCH 4
#define BH    (BATCH*HEADS)   // 64
#define BT    (BATCH*TSEQ)    // 8192
#define NT2   16              // 128-row t-tiles
#define NW4   (HEADS*CEMB*DH/4)

// qkv dynamic smem layout (halves)
#define QKV_ASTG (128*72)
#define QKV_BSTG (64*136)
#define QKV_STG_BYTES ((QKV_ASTG + QKV_BSTG) * 2)   // 35840
#define QKV_SMEM (2 * QKV_STG_BYTES)                // 71680
// pv dynamic smem (halves)
#define PV_ASTG (128*72)
#define PV_BSTG (64*72)
#define PV_STG_BYTES ((PV_ASTG + PV_BSTG) * 2)      // 27648
#define PV_SMEM (2 * PV_STG_BYTES)                  // 55296
// proj dynamic smem (halves)
#define PJ_ASTG (128*72)
#define PJ_STG_BYTES (2 * PJ_ASTG * 2)              // 36864 (A+B)
#define PJ_SMEM (2 * PJ_STG_BYTES)                  // 73728

// ---------------- scratch (device globals; allocation-free) ----------------
__device__ __align__(16) __half g_xh [(size_t)BT*CEMB];
__device__ __align__(16) __half g_wh [(size_t)3*HEADS*CEMB*DH];
__device__ __align__(16) __half g_wph[(size_t)CEMB*CEMB];
__device__ __align__(16) __half g_qh [(size_t)BH*TSEQ*DH];
__device__ __align__(16) __half g_kh [(size_t)BH*TSEQ*DH];
__device__ __align__(16) float  g_v  [(size_t)BH*TSEQ*DH];
__device__ __align__(16) __half g_vh [(size_t)BH*TSEQ*DH];
__device__ __align__(16) __half g_P  [(size_t)BH*TSEQ*TSEQ];  // 512 MiB
__device__ __align__(16) __half g_yh [(size_t)BT*CEMB];
__device__ float g_Zpart[(size_t)BH*NT2*TSEQ];

// ---------------- helpers ----------------
__device__ __forceinline__ uint32_t smem_u32(const void* p) {
    return (uint32_t)__cvta_generic_to_shared(p);
}
__device__ __forceinline__ void cpa16(uint32_t dst, const void* src) {
    asm volatile("cp.async.cg.shared.global [%0], [%1], 16;" :: "r"(dst), "l"(src));
}
#define CP_COMMIT() asm volatile("cp.async.commit_group;" ::: "memory")
#define CP_WAIT0()  asm volatile("cp.async.wait_group 0;" ::: "memory")

__device__ __forceinline__ float fast_exp(float x) {
    x = fmaxf(-60.f, fminf(60.f, x));
    float z = x * 1.4426950408889634f;
    float n = rintf(z);
    float t = (z - n) * 0.6931471805599453f;
    float p = 1.3888889e-3f;
    p = fmaf(p, t, 8.3333333e-3f);
    p = fmaf(p, t, 4.1666667e-2f);
    p = fmaf(p, t, 1.6666667e-1f);
    p = fmaf(p, t, 0.5f);
    p = fmaf(p, t, 1.0f);
    p = fmaf(p, t, 1.0f);
    return p * __int_as_float(((int)n + 127) << 23);
}
__device__ __forceinline__ void ldsm4(uint32_t r[4], uint32_t a) {
    asm volatile("ldmatrix.sync.aligned.m8n8.x4.shared.b16 {%0,%1,%2,%3},[%4];"
                 : "=r"(r[0]), "=r"(r[1]), "=r"(r[2]), "=r"(r[3]) : "r"(a));
}
__device__ __forceinline__ void ldsm4t(uint32_t r[4], uint32_t a) {
    asm volatile("ldmatrix.sync.aligned.m8n8.x4.trans.shared.b16 {%0,%1,%2,%3},[%4];"
                 : "=r"(r[0]), "=r"(r[1]), "=r"(r[2]), "=r"(r[3]) : "r"(a));
}
__device__ __forceinline__ void mma16816(float c[4], const uint32_t a[4],
                                         uint32_t b0, uint32_t b1) {
    asm volatile(
        "mma.sync.aligned.m16n8k16.row.col.f32.f16.f16.f32 "
        "{%0,%1,%2,%3},{%4,%5,%6,%7},{%8,%9},{%0,%1,%2,%3};"
        : "+f"(c[0]), "+f"(c[1]), "+f"(c[2]), "+f"(c[3])
        : "r"(a[0]), "r"(a[1]), "r"(a[2]), "r"(a[3]), "r"(b0), "r"(b1));
}

// ==================== prep kernels ====================
__global__ void cvt_kernel(const float* __restrict__ src, int n4, int sel)
{
    int i = blockIdx.x * blockDim.x + threadIdx.x;
    if (i >= n4) return;
    __half* d = (sel == 0) ? g_xh : g_wph;
    float4 v = ((const float4*)src)[i];
    __half2 a; a.x = __float2half(v.x); a.y = __float2half(v.y);
    __half2 b; b.x = __float2half(v.z); b.y = __float2half(v.w);
    ((__half2*)d)[(size_t)i * 2]     = a;
    ((__half2*)d)[(size_t)i * 2 + 1] = b;
}
__global__ void cvtw_kernel(const float* __restrict__ Wq, const float* __restrict__ Wk,
                            const float* __restrict__ Wv)
{
    int i = blockIdx.x * blockDim.x + threadIdx.x;
    if (i >= 3 * NW4) return;
    int which = i / NW4, j = i - which * NW4;
    const float* src = (which == 0) ? Wq : (which == 1) ? Wk : Wv;
    float4 v = ((const float4*)src)[j];
    __half2 a; a.x = __float2half(v.x); a.y = __float2half(v.y);
    __half2 b; b.x = __float2half(v.z); b.y = __float2half(v.w);
    ((__half2*)g_wh)[(size_t)i * 2]     = a;
    ((__half2*)g_wh)[(size_t)i * 2 + 1] = b;
}

// ==================== K1: QKV 128x128 tile, k-chunk 64, 2-stage (R16) =======
__global__ __launch_bounds__(256) void qkv_kernel()
{
    extern __shared__ __align__(16) __half sm[];
    const int tid = threadIdx.x, w = tid >> 5, lane = tid & 31;
    const int wm = w & 3, wn = w >> 2;
    const int m0 = blockIdx.x * 128;
    const int z = blockIdx.y, which = z >> 3, np = z & 7;
    const int h0 = np * 2;
    const __half* W0 = g_wh + (size_t)(which * HEADS + h0) * CEMB * DH;

    __half* A0 = sm;
    __half* B0 = sm + QKV_ASTG;

    float acc[2][8][4] = {};
    uint32_t aB[2], bB[4];
#pragma unroll
    for (int mt = 0; mt < 2; ++mt) {
        int ar = wm*32 + mt*16 + (lane & 15), ak = (lane >> 4) * 8;
        aB[mt] = smem_u32(&A0[ar*72 + ak]);
    }
#pragma unroll
    for (int blk = 0; blk < 4; ++blk) {
        int br = (lane & 15), bc = wn*64 + blk*16 + ((lane & 16) ? 8 : 0);
        bB[blk] = smem_u32(&B0[br*136 + bc]);
    }

    auto load_chunk = [&](int c, int stg) {
        const int k0 = c * 64;
        __half* As = sm + (size_t)stg * (QKV_ASTG + QKV_BSTG);
        __half* Bs = As + QKV_ASTG;
#pragma unroll
        for (int i = 0; i < 4; ++i) {
            int idx = tid + i * 256;
            {
                int r = idx >> 3, sg = (idx & 7) * 8;
                cpa16(smem_u32(&As[r*72 + sg]), &g_xh[(size_t)(m0 + r)*CEMB + k0 + sg]);
            }
            {
                int r = idx >> 4, sg = (idx & 15) * 8;
                int hh = sg >> 6, dd = sg & 63;
                cpa16(smem_u32(&Bs[r*136 + sg]),
                      &W0[(size_t)hh * CEMB * DH + (size_t)(k0 + r)*DH + dd]);
            }
        }
    };

    load_chunk(0, 0); CP_COMMIT();
    for (int c = 0; c < 16; ++c) {
        CP_WAIT0();
        __syncthreads();
        if (c + 1 < 16) { load_chunk(c + 1, (c + 1) & 1); CP_COMMIT(); }
        const uint32_t stS = (uint32_t)(c & 1) * QKV_STG_BYTES;
#pragma unroll
        for (int k16 = 0; k16 < 4; ++k16) {
            uint32_t ah[2][4], bh[4][4];
#pragma unroll
            for (int mt = 0; mt < 2; ++mt) ldsm4(ah[mt], aB[mt] + stS + k16*32);
#pragma unroll
            for (int blk = 0; blk < 4; ++blk) ldsm4t(bh[blk], bB[blk] + stS + k16*4352);
#pragma unroll
            for (int mt = 0; mt < 2; ++mt)
#pragma unroll
                for (int nt = 0; nt < 8; ++nt) {
                    int blk = nt >> 1, p2 = (nt & 1) * 2;
                    mma16816(acc[mt][nt], ah[mt], bh[blk][p2], bh[blk][p2+1]);
                }
        }
    }
#pragma unroll
    for (int mt = 0; mt < 2; ++mt)
#pragma unroll
        for (int nt = 0; nt < 8; ++nt)
#pragma unroll
            for (int half = 0; half < 2; ++half) {
                int m = m0 + wm*32 + mt*16 + (lane >> 2) + half*8;
                int n = wn*64 + nt*8 + (lane & 3)*2;
                int h = h0 + (n >> 6), d = n & 63;
                int b = m >> 11, t = m & (TSEQ - 1);
                size_t base = (((size_t)(b*HEADS + h))*TSEQ + t)*DH + d;
                float c0 = acc[mt][nt][half*2], c1 = acc[mt][nt][half*2+1];
                if (which == 2) {
                    *(float2*)&g_v[base] = make_float2(c0, c1);
                } else {
                    __half2 p2; p2.x = __float2half(c0); p2.y = __float2half(c1);
                    __half* dst = (which == 0) ? g_qh : g_kh;
                    *(__half2*)&dst[base] = p2;
                }
            }
}

// ==================== K2: scores (R9) -> P + col partials ====================
__global__ __launch_bounds__(256) void scores_kernel()
{
    __shared__ alignas(16) __half A[128*72];
    __shared__ alignas(16) __half B[64*72];
    __shared__ float red[8][32];
    const int tid = threadIdx.x, w = tid >> 5, lane = tid & 31;
    const int wm = w & 3, wn = w >> 2;
    const int bh_ = blockIdx.y;
    int p = blockIdx.x;
    int tt = (int)sqrtf((float)p);
    while (tt*tt + tt > p) --tt;
    while ((tt+1)*(tt+1) + (tt+1) <= p) ++tt;
    const int ss = p - tt*tt - tt;
    const int t0 = tt * 128, s0 = ss * 64;
    const __half* qh = g_qh + (size_t)bh_*TSEQ*DH;
    const __half* kh = g_kh + (size_t)bh_*TSEQ*DH;

    float acc[2][4][4] = {};
    uint32_t aB[2], bB[2];
#pragma unroll
    for (int mt = 0; mt < 2; ++mt) {
        int ar = wm*32 + mt*16 + (lane & 15), ak = (lane >> 4) * 8;
        aB[mt] = smem_u32(&A[ar*72 + ak]);
    }
#pragma unroll
    for (int blk = 0; blk < 2; ++blk) {
        int br = wn*32 + blk*16 + (lane & 7) + ((lane & 16) ? 8 : 0);
        int bk = (lane & 8) ? 8 : 0;
        bB[blk] = smem_u32(&B[br*72 + bk]);
    }

#pragma unroll
    for (int i = 0; i < 4; ++i) {
        int idx = tid + i * 256, r = idx >> 3, sg = (idx & 7) * 8;
        cpa16(smem_u32(&A[r*72 + sg]), &qh[(size_t)(t0 + r)*DH + sg]);
    }
#pragma unroll
    for (int i = 0; i < 2; ++i) {
        int idx = tid + i * 256, r = idx >> 3, sg = (idx & 7) * 8;
        cpa16(smem_u32(&B[r*72 + sg]), &kh[(size_t)(s0 + r)*DH + sg]);
    }
    CP_COMMIT(); CP_WAIT0();
    __syncthreads();
#pragma unroll
    for (int k16 = 0; k16 < 4; ++k16) {
        uint32_t ah[2][4], bhf[2][4];
#pragma unroll
        for (int mt = 0; mt < 2; ++mt) ldsm4(ah[mt], aB[mt] + k16*32);
#pragma unroll
        for (int blk = 0; blk < 2; ++blk) ldsm4(bhf[blk], bB[blk] + k16*32);
#pragma unroll
        for (int mt = 0; mt < 2; ++mt)
#pragma unroll
            for (int nt = 0; nt < 4; ++nt) {
                int blk = nt >> 1, p2 = (nt & 1) * 2;
                mma16816(acc[mt][nt], ah[mt], bhf[blk][p2], bhf[blk][p2+1]);
            }
    }

    const float scale = 0.03125f;
    float cs[4][2] = {};
    size_t Pbase = (size_t)bh_ * TSEQ * TSEQ;
#pragma unroll
    for (int mt = 0; mt < 2; ++mt)
#pragma unroll
        for (int nt = 0; nt < 4; ++nt)
#pragma unroll
            for (int half = 0; half < 2; ++half) {
                int t = t0 + wm*32 + mt*16 + (lane >> 2) + half*8;
                int s = s0 + wn*32 + nt*8 + (lane & 3)*2;
                float e0 = (s     <= t) ? fast_exp(acc[mt][nt][half*2]   * scale) : 0.f;
                float e1 = (s + 1 <= t) ? fast_exp(acc[mt][nt][half*2+1] * scale) : 0.f;
                cs[nt][0] += e0; cs[nt][1] += e1;
                __half2 p2; p2.x = __float2half(e0); p2.y = __float2half(e1);
                *(__half2*)&g_P[Pbase + (size_t)t*TSEQ + s] = p2;
            }
#pragma unroll
    for (int nt = 0; nt < 4; ++nt)
#pragma unroll
        for (int par = 0; par < 2; ++par) {
            float v = cs[nt][par];
            v += __shfl_xor_sync(0xffffffffu, v, 4);
            v += __shfl_xor_sync(0xffffffffu, v, 8);
            v += __shfl_xor_sync(0xffffffffu, v, 16);
            if (lane < 4) red[w][nt*8 + (lane & 3)*2 + par] = v;
        }
    __syncthreads();
    if (tid < 64) {
        int col = tid, wh = col >> 5;
        float s = red[wh*4+0][col & 31] + red[wh*4+1][col & 31]
                + red[wh*4+2][col & 31] + red[wh*4+3][col & 31];
        g_Zpart[((size_t)bh_*NT2 + tt)*TSEQ + s0 + col] = s;
    }
}

// ==================== K3: fused Z-reduce + v scale ====================
// One thread per (bh, s) row: Z = sum partials (tt ascending, same order),
// then scale the row's 64 v elements (same per-element math as before).
__global__ void zvscale_kernel()
{
    int idx = blockIdx.x * blockDim.x + threadIdx.x;
    if (idx >= BH * TSEQ) return;
    int bh_ = idx >> 11, s = idx & (TSEQ - 1), ttmin = s >> 7;
    float sum = 0.f;
    for (int tt = ttmin; tt < NT2; ++tt)
        sum += g_Zpart[((size_t)bh_*NT2 + tt)*TSEQ + s];
    float rz = 1.0f / sum;
    size_t row4 = (size_t)idx * 16;   // 16 float4 per 64-elem row
#pragma unroll
    for (int j = 0; j < 16; ++j) {
        float4 v = ((const float4*)g_v)[row4 + j];
        __half2 a; a.x = __float2half(v.x * rz); a.y = __float2half(v.y * rz);
        __half2 b; b.x = __float2half(v.z * rz); b.y = __float2half(v.w * rz);
        ((__half2*)g_vh)[(row4 + j) * 2]     = a;
        ((__half2*)g_vh)[(row4 + j) * 2 + 1] = b;
    }
}

// ==================== K4: y = P @ vh, s-chunk 64, 2-stage ===================
// grid(16, 64). nsteps = 2(tt+1). Dynamic smem: A 128x64 pitch72 + B 64x64 pitch72.
__global__ __launch_bounds__(256) void pv_kernel()
{
    extern __shared__ __align__(16) __half sm[];
    const int tid = threadIdx.x, w = tid >> 5, lane = tid & 31;
    const int wm = w & 3, wn = w >> 2;
    const int tt = 15 - blockIdx.x;
    const int bh_ = blockIdx.y;
    const int t0 = tt * 128;
    const __half* Pp = g_P + (size_t)bh_*TSEQ*TSEQ;
    const __half* vh = g_vh + (size_t)bh_*TSEQ*DH;

    __half* A0 = sm;
    __half* B0 = sm + PV_ASTG;

    float acc[2][4][4] = {};
    uint32_t aB[2], bB[2];
#pragma unroll
    for (int mt = 0; mt < 2; ++mt) {
        int ar = wm*32 + mt*16 + (lane & 15), ak = (lane >> 4) * 8;
        aB[mt] = smem_u32(&A0[ar*72 + ak]);
    }
#pragma unroll
    for (int blk = 0; blk < 2; ++blk) {  // trans-B: row=k(s), col=n(d)
        int br = (lane & 15), bc = wn*32 + blk*16 + ((lane & 16) ? 8 : 0);
        bB[blk] = smem_u32(&B0[br*72 + bc]);
    }

    const int nsteps = 2 * (tt + 1);
    auto load_chunk = [&](int st, int stg) {
        const int s0 = st * 64;
        __half* As = sm + (size_t)stg * (PV_ASTG + PV_BSTG);
        __half* Bs = As + PV_ASTG;
#pragma unroll
        for (int i = 0; i < 4; ++i) {
            int idx = tid + i * 256, r = idx >> 3, sg = (idx & 7) * 8;
            cpa16(smem_u32(&As[r*72 + sg]), &Pp[(size_t)(t0 + r)*TSEQ + s0 + sg]);
        }
#pragma unroll
        for (int i = 0; i < 2; ++i) {
            int idx = tid + i * 256, r = idx >> 3, sg = (idx & 7) * 8;
            cpa16(smem_u32(&Bs[r*72 + sg]), &vh[(size_t)(s0 + r)*DH + sg]);
        }
    };

    load_chunk(0, 0); CP_COMMIT();
    for (int c = 0; c < nsteps; ++c) {
        CP_WAIT0();
        __syncthreads();
        if (c + 1 < nsteps) { load_chunk(c + 1, (c + 1) & 1); CP_COMMIT(); }
        const uint32_t stS = (uint32_t)(c & 1) * PV_STG_BYTES;
#pragma unroll
        for (int k16 = 0; k16 < 4; ++k16) {
            uint32_t ah[2][4], bhf[2][4];
#pragma unroll
            for (int mt = 0; mt < 2; ++mt) ldsm4(ah[mt], aB[mt] + stS + k16*32);
#pragma unroll
            for (int blk = 0; blk < 2; ++blk) ldsm4t(bhf[blk], bB[blk] + stS + k16*2304);
#pragma unroll
            for (int mt = 0; mt < 2; ++mt)
#pragma unroll
                for (int nt = 0; nt < 4; ++nt) {
                    int blk = nt >> 1, p2 = (nt & 1) * 2;
                    mma16816(acc[mt][nt], ah[mt], bhf[blk][p2], bhf[blk][p2+1]);
                }
        }
    }
    const int b = bh_ >> 4, h = bh_ & 15;
#pragma unroll
    for (int mt = 0; mt < 2; ++mt)
#pragma unroll
        for (int nt = 0; nt < 4; ++nt)
#pragma unroll
            for (int half = 0; half < 2; ++half) {
                int t = t0 + wm*32 + mt*16 + (lane >> 2) + half*8;
                int n = wn*32 + nt*8 + (lane & 3)*2;
                size_t o = ((size_t)(b*TSEQ + t))*CEMB + h*DH + n;
                __half2 p2;
                p2.x = __float2half(acc[mt][nt][half*2]);
                p2.y = __float2half(acc[mt][nt][half*2+1]);
                *(__half2*)&g_yh[o] = p2;
            }
}

// ==================== K5: proj 128x128 tile, k-chunk 64, 2-stage ============
// grid(BT/128, CEMB/128). Dynamic smem: A,B each 128x64 pitch72 per stage.
__global__ __launch_bounds__(256) void proj_kernel(
    const float* __restrict__ bp, float* __restrict__ out)
{
    extern __shared__ __align__(16) __half sm[];
    const int tid = threadIdx.x, w = tid >> 5, lane = tid & 31;
    const int wm = w & 3, wn = w >> 2;          // warp tile 32m x 64n
    const int m0 = blockIdx.x * 128, n0 = blockIdx.y * 128;

    __half* A0 = sm;
    __half* B0 = sm + PJ_ASTG;

    float acc[2][8][4] = {};
    uint32_t aB[2], bB[4];
#pragma unroll
    for (int mt = 0; mt < 2; ++mt) {
        int ar = wm*32 + mt*16 + (lane & 15), ak = (lane >> 4) * 8;
        aB[mt] = smem_u32(&A0[ar*72 + ak]);
    }
#pragma unroll
    for (int blk = 0; blk < 4; ++blk) {  // natural B: row=n, col=k
        int br = wn*64 + blk*16 + (lane & 7) + ((lane & 16) ? 8 : 0);
        int bk = (lane & 8) ? 8 : 0;
        bB[blk] = smem_u32(&B0[br*72 + bk]);
    }

    auto load_chunk = [&](int c, int stg) {
        const int k0 = c * 64;
        __half* As = sm + (size_t)stg * (2 * PJ_ASTG);
        __half* Bs = As + PJ_ASTG;
#pragma unroll
        for (int i = 0; i < 4; ++i) {
            int idx = tid + i * 256, r = idx >> 3, sg = (idx & 7) * 8;
            cpa16(smem_u32(&As[r*72 + sg]), &g_yh[(size_t)(m0 + r)*CEMB + k0 + sg]);
            cpa16(smem_u32(&Bs[r*72 + sg]), &g_wph[(size_t)(n0 + r)*CEMB + k0 + sg]);
        }
    };

    load_chunk(0, 0); CP_COMMIT();
    for (int c = 0; c < 16; ++c) {
        CP_WAIT0();
        __syncthreads();
        if (c + 1 < 16) { load_chunk(c + 1, (c + 1) & 1); CP_COMMIT(); }
        const uint32_t stS = (uint32_t)(c & 1) * PJ_STG_BYTES;
#pragma unroll
        for (int k16 = 0; k16 < 4; ++k16) {
            uint32_t ah[2][4], bhf[4][4];
#pragma unroll
            for (int mt = 0; mt < 2; ++mt) ldsm4(ah[mt], aB[mt] + stS + k16*32);
#pragma unroll
            for (int blk = 0; blk < 4; ++blk) ldsm4(bhf[blk], bB[blk] + stS + k16*32);
#pragma unroll
            for (int mt = 0; mt < 2; ++mt)
#pragma unroll
                for (int nt = 0; nt < 8; ++nt) {
                    int blk = nt >> 1, p2 = (nt & 1) * 2;
                    mma16816(acc[mt][nt], ah[mt], bhf[blk][p2], bhf[blk][p2+1]);
                }
        }
    }
#pragma unroll
    for (int mt = 0; mt < 2; ++mt)
#pragma unroll
        for (int nt = 0; nt < 8; ++nt) {
            int n = n0 + wn*64 + nt*8 + (lane & 3)*2;
            float b0 = bp[n], b1 = bp[n + 1];
#pragma unroll
            for (int half = 0; half < 2; ++half) {
                int m = m0 + wm*32 + mt*16 + (lane >> 2) + half*8;
                size_t o = (size_t)m*CEMB + n;
                *(float2*)&out[o] = make_float2(acc[mt][nt][half*2] + b0,
                                                acc[mt][nt][half*2+1] + b1);
            }
        }
}

// ==================== launch ====================
extern "C" void kernel_launch(void* const* d_in, const int* in_sizes, int n_in,
                              void* d_out, int out_size)
{
    const float* x  = (const float*)d_in[0];
    const float* Wq = (const float*)d_in[1];
    const float* Wk = (const float*)d_in[2];
    const float* Wv = (const float*)d_in[3];
    const float* Wp = (const float*)d_in[4];
    const float* bp = (const float*)d_in[5];
    float* out = (float*)d_out;

    // host-side attributes (not stream ops; graph-capture safe; idempotent)
    cudaFuncSetAttribute(qkv_kernel,
                         cudaFuncAttributeMaxDynamicSharedMemorySize, QKV_SMEM);
    cudaFuncSetAttribute(pv_kernel,
                         cudaFuncAttributeMaxDynamicSharedMemorySize, PV_SMEM);
    cudaFuncSetAttribute(proj_kernel,
                         cudaFuncAttributeMaxDynamicSharedMemorySize, PJ_SMEM);

    cvt_kernel<<<(BT*CEMB/4 + 255)/256, 256>>>(x, BT*CEMB/4, 0);
    cvtw_kernel<<<(3*NW4 + 255)/256, 256>>>(Wq, Wk, Wv);
    cvt_kernel<<<(CEMB*CEMB/4 + 255)/256, 256>>>(Wp, CEMB*CEMB/4, 2);

    qkv_kernel<<<dim3(BT/128, 24), 256, QKV_SMEM>>>();
    scores_kernel<<<dim3(272, BH), 256>>>();
    zvscale_kernel<<<(BH*TSEQ + 255)/256, 256>>>();
    pv_kernel<<<dim3(16, BH), 256, PV_SMEM>>>();
    proj_kernel<<<dim3(BT/128, CEMB/128), 256, PJ_SMEM>>>(bp, out);
}